// round 1
// baseline (speedup 1.0000x reference)
#include <cuda_runtime.h>
#include <math.h>

#define B_ 2
#define S_ 1024
#define D_ 2048
#define H_ 16
#define DH_ 128
#define E_ 8
#define I_ 1408
#define IS_ 5632
#define T_ (B_*S_)
#define EPS_ 1e-6f

// ---------------- static device scratch (allocation-free rule) ----------------
__device__ float g_h1[T_*D_];          // rmsnorm1 out
__device__ float g_qm[T_*D_];          // Q (post-rope)
__device__ float g_km[T_*D_];          // K (post-rope)
__device__ float g_vm[T_*D_];          // V
__device__ float g_attn[T_*D_];        // attention out (pre o-proj)
__device__ float g_h[T_*D_];           // x + attn@o_w
__device__ float g_h2[T_*D_];          // rmsnorm2 out
__device__ float g_moe[T_*D_];         // routed-expert accumulator
__device__ float g_G[T_*IS_];          // gate buffer (ld=I_ for MoE, ld=IS_ for shared)
__device__ float g_U[T_*IS_];          // up buffer
__device__ float g_scores[B_*H_*S_*S_];
__device__ float g_sgate[T_];
__device__ int   g_cnt[E_];
__device__ int   g_list[E_*T_];
__device__ float g_wlist[E_*T_];

// ---------------- generic 128x128x8 SGEMM ----------------
// A [M,K] row-major (lda), B [K,N] row-major (ldb), C [M,N] row-major (ldc)
// batch: z1 = z/zdiv, z2 = z%zdiv; ptr += z1*s?1 + z2*s?2
// MODE 0: C = A@B ; MODE 1: C = A@B + X[col] (bias) ; MODE 2: C = A@B + X[row,col]
// All generic uses have M,N multiples of 128 and K multiple of 8 -> no guards.
struct GemmP {
    const float* A; const float* B; float* C; const float* X;
    int lda, ldb, ldc;
    int M, N, K;
    int zdiv;
    long long sA1, sA2, sB1, sB2, sC1, sC2;
};

template<int MODE>
__global__ __launch_bounds__(256)
void sgemm_k(GemmP p)
{
    __shared__ float As[8][128];
    __shared__ float Bs[8][128];
    int tid = threadIdx.x;
    int z = blockIdx.z;
    int z1 = z / p.zdiv, z2 = z - z1 * p.zdiv;
    const float* A  = p.A + z1*p.sA1 + z2*p.sA2;
    const float* Bm = p.B + z1*p.sB1 + z2*p.sB2;
    float*       C  = p.C + z1*p.sC1 + z2*p.sC2;
    const float* X  = p.X;
    if (MODE == 2) X += z1*p.sC1 + z2*p.sC2;

    int row0 = blockIdx.y * 128, col0 = blockIdx.x * 128;
    int aRow = tid >> 1, aCol = (tid & 1) * 4;
    int bRow = tid >> 5, bCol = (tid & 31) * 4;
    int ty = tid >> 4, tx = tid & 15;

    float acc[8][8];
    #pragma unroll
    for (int i = 0; i < 8; i++)
        #pragma unroll
        for (int j = 0; j < 8; j++) acc[i][j] = 0.f;

    const float* Aptr = A + (long long)(row0 + aRow) * p.lda + aCol;
    const float* Bptr = Bm + (long long)bRow * p.ldb + col0 + bCol;

    for (int k0 = 0; k0 < p.K; k0 += 8) {
        float4 av = *(const float4*)(Aptr + k0);
        float4 bv = *(const float4*)(Bptr + (long long)k0 * p.ldb);
        As[aCol+0][aRow] = av.x; As[aCol+1][aRow] = av.y;
        As[aCol+2][aRow] = av.z; As[aCol+3][aRow] = av.w;
        *(float4*)&Bs[bRow][bCol] = bv;
        __syncthreads();
        #pragma unroll
        for (int kk = 0; kk < 8; kk++) {
            float a[8], b[8];
            *(float4*)(a)   = *(const float4*)&As[kk][ty*8];
            *(float4*)(a+4) = *(const float4*)&As[kk][ty*8+4];
            *(float4*)(b)   = *(const float4*)&Bs[kk][tx*8];
            *(float4*)(b+4) = *(const float4*)&Bs[kk][tx*8+4];
            #pragma unroll
            for (int i = 0; i < 8; i++)
                #pragma unroll
                for (int j = 0; j < 8; j++)
                    acc[i][j] += a[i] * b[j];
        }
        __syncthreads();
    }
    #pragma unroll
    for (int i = 0; i < 8; i++) {
        long long ro = (long long)(row0 + ty*8 + i) * p.ldc;
        #pragma unroll
        for (int j = 0; j < 8; j++) {
            int c = col0 + tx*8 + j;
            float v = acc[i][j];
            if (MODE == 1) v += X[c];
            if (MODE == 2) v += X[ro + c];
            C[ro + c] = v;
        }
    }
}

// ---------------- rmsnorm ----------------
__global__ void rmsnorm_k(const float* __restrict__ x, const float* __restrict__ w,
                          float* __restrict__ out)
{
    int t = blockIdx.x, tid = threadIdx.x;
    const float* xr = x + (long long)t * D_;
    float s = 0.f;
    #pragma unroll
    for (int i = 0; i < 8; i++) { float v = xr[tid + i*256]; s += v * v; }
    __shared__ float red[256];
    red[tid] = s; __syncthreads();
    for (int st = 128; st > 0; st >>= 1) {
        if (tid < st) red[tid] += red[tid + st];
        __syncthreads();
    }
    float r = rsqrtf(red[0] / (float)D_ + EPS_);
    float* orow = out + (long long)t * D_;
    #pragma unroll
    for (int i = 0; i < 8; i++) { int d = tid + i*256; orow[d] = xr[d] * r * w[d]; }
}

// ---------------- rope (in-place on g_qm, g_km) ----------------
__global__ void rope_k(const int* __restrict__ pos,
                       const float* __restrict__ sint, const float* __restrict__ cost)
{
    int idx = blockIdx.x * blockDim.x + threadIdx.x;   // over T_*H_*64
    int d  = idx & 63;
    int hh = (idx >> 6) & 15;
    int t  = idx >> 10;
    int p = pos[t];
    long long base = (long long)t * D_ + hh * DH_;
    float c1 = cost[p*DH_ + d],      s1 = sint[p*DH_ + d];
    float c2 = cost[p*DH_ + d + 64], s2 = sint[p*DH_ + d + 64];
    float q1 = g_qm[base + d], q2 = g_qm[base + d + 64];
    g_qm[base + d]      = q1 * c1 - q2 * s1;
    g_qm[base + d + 64] = q2 * c2 + q1 * s2;
    float k1 = g_km[base + d], k2 = g_km[base + d + 64];
    g_km[base + d]      = k1 * c1 - k2 * s1;
    g_km[base + d + 64] = k2 * c2 + k1 * s2;
}

// ---------------- attention scores (causal + mask) ----------------
__global__ __launch_bounds__(256)
void scores_k(const float* __restrict__ q, const float* __restrict__ kmat,
              const int* __restrict__ amask)
{
    int z = blockIdx.z; int b = z >> 4; int h = z & 15;
    const float* A  = q    + (long long)b * S_ * D_ + h * DH_;
    const float* Bm = kmat + (long long)b * S_ * D_ + h * DH_;
    float* C = g_scores + (long long)z * S_ * S_;
    int row0 = blockIdx.y * 128, col0 = blockIdx.x * 128;
    int tid = threadIdx.x;
    int ty = tid >> 4, tx = tid & 15;

    if (col0 > row0 + 127) {   // fully above diagonal -> masked
        #pragma unroll
        for (int i = 0; i < 8; i++) {
            long long ro = (long long)(row0 + ty*8 + i) * S_;
            #pragma unroll
            for (int j = 0; j < 8; j++) C[ro + col0 + tx*8 + j] = -1e30f;
        }
        return;
    }
    __shared__ float As[8][128];
    __shared__ float Bs[8][128];
    int aRow = tid >> 1, aCol = (tid & 1) * 4;
    float acc[8][8];
    #pragma unroll
    for (int i = 0; i < 8; i++)
        #pragma unroll
        for (int j = 0; j < 8; j++) acc[i][j] = 0.f;

    for (int k0 = 0; k0 < DH_; k0 += 8) {
        float4 av = *(const float4*)(A  + (long long)(row0 + aRow)*D_ + k0 + aCol);
        float4 bv = *(const float4*)(Bm + (long long)(col0 + aRow)*D_ + k0 + aCol);
        As[aCol+0][aRow] = av.x; As[aCol+1][aRow] = av.y;
        As[aCol+2][aRow] = av.z; As[aCol+3][aRow] = av.w;
        Bs[aCol+0][aRow] = bv.x; Bs[aCol+1][aRow] = bv.y;
        Bs[aCol+2][aRow] = bv.z; Bs[aCol+3][aRow] = bv.w;
        __syncthreads();
        #pragma unroll
        for (int kk = 0; kk < 8; kk++) {
            float a[8], b[8];
            *(float4*)(a)   = *(const float4*)&As[kk][ty*8];
            *(float4*)(a+4) = *(const float4*)&As[kk][ty*8+4];
            *(float4*)(b)   = *(const float4*)&Bs[kk][tx*8];
            *(float4*)(b+4) = *(const float4*)&Bs[kk][tx*8+4];
            #pragma unroll
            for (int i = 0; i < 8; i++)
                #pragma unroll
                for (int j = 0; j < 8; j++)
                    acc[i][j] += a[i] * b[j];
        }
        __syncthreads();
    }
    const float scale = 0.08838834764831845f;  // 1/sqrt(128)
    #pragma unroll
    for (int i = 0; i < 8; i++) {
        int r = row0 + ty*8 + i;
        long long ro = (long long)r * S_;
        #pragma unroll
        for (int j = 0; j < 8; j++) {
            int c = col0 + tx*8 + j;
            bool ok = (c <= r) && (amask[b*S_ + c] != 0);
            C[ro + c] = ok ? acc[i][j] * scale : -1e30f;
        }
    }
}

// ---------------- softmax (row-wise over S) ----------------
__global__ void softmax_k()
{
    long long row = blockIdx.x;
    float* p = g_scores + row * S_;
    int tid = threadIdx.x;
    __shared__ float red[256];
    float lv[4];
    #pragma unroll
    for (int i = 0; i < 4; i++) lv[i] = p[tid + i*256];
    float m = fmaxf(fmaxf(lv[0], lv[1]), fmaxf(lv[2], lv[3]));
    red[tid] = m; __syncthreads();
    for (int s = 128; s > 0; s >>= 1) {
        if (tid < s) red[tid] = fmaxf(red[tid], red[tid + s]);
        __syncthreads();
    }
    float mx = red[0]; __syncthreads();
    float sum = 0.f;
    #pragma unroll
    for (int i = 0; i < 4; i++) { lv[i] = expf(lv[i] - mx); sum += lv[i]; }
    red[tid] = sum; __syncthreads();
    for (int s = 128; s > 0; s >>= 1) {
        if (tid < s) red[tid] += red[tid + s];
        __syncthreads();
    }
    float inv = 1.0f / red[0];
    #pragma unroll
    for (int i = 0; i < 4; i++) p[tid + i*256] = lv[i] * inv;
}

// ---------------- zero MoE state ----------------
__global__ void zero_k()
{
    long long i = (long long)blockIdx.x * 256 + threadIdx.x;
    g_moe[i] = 0.f;
    if (i < E_) g_cnt[i] = 0;
}

// ---------------- router: logits -> softmax -> top2 -> expert lists ----------------
__global__ void router_k(const float* __restrict__ rw)
{
    int t = blockIdx.x, tid = threadIdx.x;
    __shared__ float red[256 * 8];
    float loc[8];
    #pragma unroll
    for (int e = 0; e < 8; e++) loc[e] = 0.f;
    const float* xr = g_h2 + (long long)t * D_;
    for (int d = tid; d < D_; d += 256) {
        float xv = xr[d];
        #pragma unroll
        for (int e = 0; e < 8; e++) loc[e] += xv * rw[d*E_ + e];
    }
    #pragma unroll
    for (int e = 0; e < 8; e++) red[e*256 + tid] = loc[e];
    __syncthreads();
    for (int s = 128; s > 0; s >>= 1) {
        if (tid < s) {
            #pragma unroll
            for (int e = 0; e < 8; e++) red[e*256 + tid] += red[e*256 + tid + s];
        }
        __syncthreads();
    }
    if (tid == 0) {
        float lg[8], pr[8];
        #pragma unroll
        for (int e = 0; e < 8; e++) lg[e] = red[e*256];
        float mx = lg[0];
        #pragma unroll
        for (int e = 1; e < 8; e++) mx = fmaxf(mx, lg[e]);
        float se = 0.f;
        #pragma unroll
        for (int e = 0; e < 8; e++) { pr[e] = expf(lg[e] - mx); se += pr[e]; }
        #pragma unroll
        for (int e = 0; e < 8; e++) pr[e] /= se;
        int i1 = 0;
        #pragma unroll
        for (int e = 1; e < 8; e++) if (pr[e] > pr[i1]) i1 = e;  // first-index tiebreak (matches top_k)
        int i2 = (i1 == 0) ? 1 : 0;
        #pragma unroll
        for (int e = 0; e < 8; e++) if (e != i1 && pr[e] > pr[i2]) i2 = e;
        int s1 = atomicAdd(&g_cnt[i1], 1);
        g_list[i1*T_ + s1] = t; g_wlist[i1*T_ + s1] = pr[i1];
        int s2 = atomicAdd(&g_cnt[i2], 1);
        g_list[i2*T_ + s2] = t; g_wlist[i2*T_ + s2] = pr[i2];
    }
}

// ---------------- shared-expert sigmoid gate ----------------
__global__ void sgate_k(const float* __restrict__ gw)
{
    int t = blockIdx.x, tid = threadIdx.x;
    const float* xr = g_h2 + (long long)t * D_;
    float s = 0.f;
    #pragma unroll
    for (int i = 0; i < 8; i++) { int d = tid + i*256; s += xr[d] * gw[d]; }
    __shared__ float red[256];
    red[tid] = s; __syncthreads();
    for (int st = 128; st > 0; st >>= 1) {
        if (tid < st) red[tid] += red[tid + st];
        __syncthreads();
    }
    if (tid == 0) g_sgate[t] = 1.f / (1.f + expf(-red[0]));
}

// ---------------- MoE gathered gate/up GEMM (per expert) ----------------
// Cout[m, 0:I_] = g_h2[list[m], :] @ W  (W = eg/eu weight of this expert, [D_, I_])
__global__ __launch_bounds__(256)
void moe_gu_k(const float* __restrict__ W, int e, float* __restrict__ Cout)
{
    int M = g_cnt[e];
    int row0 = blockIdx.y * 128;
    if (row0 >= M) return;
    int col0 = blockIdx.x * 128;
    __shared__ float As[8][128];
    __shared__ float Bs[8][128];
    __shared__ int toks[128];
    int tid = threadIdx.x;
    if (tid < 128) {
        int r = row0 + tid;
        toks[tid] = (r < M) ? g_list[e*T_ + r] : 0;
    }
    __syncthreads();
    int aRow = tid >> 1, aCol = (tid & 1) * 4;
    int bRow = tid >> 5, bCol = (tid & 31) * 4;
    int ty = tid >> 4, tx = tid & 15;
    float acc[8][8];
    #pragma unroll
    for (int i = 0; i < 8; i++)
        #pragma unroll
        for (int j = 0; j < 8; j++) acc[i][j] = 0.f;
    int tok = toks[aRow];
    for (int k0 = 0; k0 < D_; k0 += 8) {
        float4 av = *(const float4*)(g_h2 + (long long)tok * D_ + k0 + aCol);
        float4 bv = *(const float4*)(W + (long long)(k0 + bRow) * I_ + col0 + bCol);
        As[aCol+0][aRow] = av.x; As[aCol+1][aRow] = av.y;
        As[aCol+2][aRow] = av.z; As[aCol+3][aRow] = av.w;
        *(float4*)&Bs[bRow][bCol] = bv;
        __syncthreads();
        #pragma unroll
        for (int kk = 0; kk < 8; kk++) {
            float a[8], b[8];
            *(float4*)(a)   = *(const float4*)&As[kk][ty*8];
            *(float4*)(a+4) = *(const float4*)&As[kk][ty*8+4];
            *(float4*)(b)   = *(const float4*)&Bs[kk][tx*8];
            *(float4*)(b+4) = *(const float4*)&Bs[kk][tx*8+4];
            #pragma unroll
            for (int i = 0; i < 8; i++)
                #pragma unroll
                for (int j = 0; j < 8; j++)
                    acc[i][j] += a[i] * b[j];
        }
        __syncthreads();
    }
    #pragma unroll
    for (int i = 0; i < 8; i++) {
        int r = row0 + ty*8 + i;
        if (r < M) {
            long long ro = (long long)r * I_;
            #pragma unroll
            for (int j = 0; j < 8; j++)
                Cout[ro + col0 + tx*8 + j] = acc[i][j];
        }
    }
}

// ---------------- MoE down GEMM + scatter (per expert) ----------------
// g_moe[list[m], :] += (silu(G[m,:]) * U[m,:] * w[m]) @ Wd   (Wd [I_, D_])
__global__ __launch_bounds__(256)
void moe_down_k(const float* __restrict__ Wd, int e)
{
    int M = g_cnt[e];
    int row0 = blockIdx.y * 128;
    if (row0 >= M) return;
    int col0 = blockIdx.x * 128;
    __shared__ float As[8][128];
    __shared__ float Bs[8][128];
    __shared__ int toks[128];
    __shared__ float wexp[128];
    int tid = threadIdx.x;
    if (tid < 128) {
        int r = row0 + tid;
        toks[tid] = (r < M) ? g_list[e*T_ + r] : 0;
        wexp[tid] = (r < M) ? g_wlist[e*T_ + r] : 0.f;
    }
    __syncthreads();
    int aRow = tid >> 1, aCol = (tid & 1) * 4;
    int bRow = tid >> 5, bCol = (tid & 31) * 4;
    int ty = tid >> 4, tx = tid & 15;
    float acc[8][8];
    #pragma unroll
    for (int i = 0; i < 8; i++)
        #pragma unroll
        for (int j = 0; j < 8; j++) acc[i][j] = 0.f;
    float wq = wexp[aRow];
    long long arow_off = (long long)(row0 + aRow) * I_ + aCol;
    for (int k0 = 0; k0 < I_; k0 += 8) {
        float4 gv = *(const float4*)(g_G + arow_off + k0);
        float4 uv = *(const float4*)(g_U + arow_off + k0);
        float4 av;
        av.x = (gv.x / (1.f + expf(-gv.x))) * uv.x * wq;
        av.y = (gv.y / (1.f + expf(-gv.y))) * uv.y * wq;
        av.z = (gv.z / (1.f + expf(-gv.z))) * uv.z * wq;
        av.w = (gv.w / (1.f + expf(-gv.w))) * uv.w * wq;
        float4 bv = *(const float4*)(Wd + (long long)(k0 + bRow) * D_ + col0 + bCol);
        As[aCol+0][aRow] = av.x; As[aCol+1][aRow] = av.y;
        As[aCol+2][aRow] = av.z; As[aCol+3][aRow] = av.w;
        *(float4*)&Bs[bRow][bCol] = bv;
        __syncthreads();
        #pragma unroll
        for (int kk = 0; kk < 8; kk++) {
            float a[8], b[8];
            *(float4*)(a)   = *(const float4*)&As[kk][ty*8];
            *(float4*)(a+4) = *(const float4*)&As[kk][ty*8+4];
            *(float4*)(b)   = *(const float4*)&Bs[kk][tx*8];
            *(float4*)(b+4) = *(const float4*)&Bs[kk][tx*8+4];
            #pragma unroll
            for (int i = 0; i < 8; i++)
                #pragma unroll
                for (int j = 0; j < 8; j++)
                    acc[i][j] += a[i] * b[j];
        }
        __syncthreads();
    }
    #pragma unroll
    for (int i = 0; i < 8; i++) {
        int r = row0 + ty*8 + i;
        if (r < M) {
            int t = toks[ty*8 + i];
            long long ro = (long long)t * D_;
            #pragma unroll
            for (int j = 0; j < 8; j++) {
                int c = col0 + tx*8 + j;
                g_moe[ro + c] += acc[i][j];   // unique (t,c) per launch; launches serialize
            }
        }
    }
}

// ---------------- shared-expert down GEMM + final combine ----------------
// out[t,:] = g_h[t,:] + g_moe[t,:] + sgate[t] * ((silu(G2)*U2)[t,:] @ sd_w)
__global__ __launch_bounds__(256)
void shared_down_k(const float* __restrict__ Wd, float* __restrict__ out)
{
    int row0 = blockIdx.y * 128, col0 = blockIdx.x * 128;
    __shared__ float As[8][128];
    __shared__ float Bs[8][128];
    int tid = threadIdx.x;
    int aRow = tid >> 1, aCol = (tid & 1) * 4;
    int bRow = tid >> 5, bCol = (tid & 31) * 4;
    int ty = tid >> 4, tx = tid & 15;
    float acc[8][8];
    #pragma unroll
    for (int i = 0; i < 8; i++)
        #pragma unroll
        for (int j = 0; j < 8; j++) acc[i][j] = 0.f;
    long long arow_off = (long long)(row0 + aRow) * IS_ + aCol;
    for (int k0 = 0; k0 < IS_; k0 += 8) {
        float4 gv = *(const float4*)(g_G + arow_off + k0);
        float4 uv = *(const float4*)(g_U + arow_off + k0);
        float4 av;
        av.x = (gv.x / (1.f + expf(-gv.x))) * uv.x;
        av.y = (gv.y / (1.f + expf(-gv.y))) * uv.y;
        av.z = (gv.z / (1.f + expf(-gv.z))) * uv.z;
        av.w = (gv.w / (1.f + expf(-gv.w))) * uv.w;
        float4 bv = *(const float4*)(Wd + (long long)(k0 + bRow) * D_ + col0 + bCol);
        As[aCol+0][aRow] = av.x; As[aCol+1][aRow] = av.y;
        As[aCol+2][aRow] = av.z; As[aCol+3][aRow] = av.w;
        *(float4*)&Bs[bRow][bCol] = bv;
        __syncthreads();
        #pragma unroll
        for (int kk = 0; kk < 8; kk++) {
            float a[8], b[8];
            *(float4*)(a)   = *(const float4*)&As[kk][ty*8];
            *(float4*)(a+4) = *(const float4*)&As[kk][ty*8+4];
            *(float4*)(b)   = *(const float4*)&Bs[kk][tx*8];
            *(float4*)(b+4) = *(const float4*)&Bs[kk][tx*8+4];
            #pragma unroll
            for (int i = 0; i < 8; i++)
                #pragma unroll
                for (int j = 0; j < 8; j++)
                    acc[i][j] += a[i] * b[j];
        }
        __syncthreads();
    }
    #pragma unroll
    for (int i = 0; i < 8; i++) {
        int r = row0 + ty*8 + i;
        float sg = g_sgate[r];
        long long ro = (long long)r * D_;
        #pragma unroll
        for (int j = 0; j < 8; j++) {
            int c = col0 + tx*8 + j;
            out[ro + c] = g_h[ro + c] + g_moe[ro + c] + sg * acc[i][j];
        }
    }
}

// ---------------- host launcher ----------------
extern "C" void kernel_launch(void* const* d_in, const int* in_sizes, int n_in,
                              void* d_out, int out_size)
{
    const float* x    = (const float*)d_in[0];
    const int*   pos  = (const int*)  d_in[1];
    const int*   am   = (const int*)  d_in[2];
    const float* sint = (const float*)d_in[3];
    const float* cost = (const float*)d_in[4];
    const float* ln1  = (const float*)d_in[5];
    const float* ln2  = (const float*)d_in[6];
    const float* qw   = (const float*)d_in[7];
    const float* qbias= (const float*)d_in[8];
    const float* kw   = (const float*)d_in[9];
    const float* kbias= (const float*)d_in[10];
    const float* vw   = (const float*)d_in[11];
    const float* vbias= (const float*)d_in[12];
    const float* ow   = (const float*)d_in[13];
    const float* rw   = (const float*)d_in[14];
    const float* eg   = (const float*)d_in[15];
    const float* eu   = (const float*)d_in[16];
    const float* ed   = (const float*)d_in[17];
    const float* sg   = (const float*)d_in[18];
    const float* su   = (const float*)d_in[19];
    const float* sd   = (const float*)d_in[20];
    const float* sgw  = (const float*)d_in[21];
    float* out = (float*)d_out;
    (void)in_sizes; (void)n_in; (void)out_size;

    float *h1, *qm, *km, *vm, *attn, *hb, *h2, *Gp, *Up, *sc;
    cudaGetSymbolAddress((void**)&h1,   g_h1);
    cudaGetSymbolAddress((void**)&qm,   g_qm);
    cudaGetSymbolAddress((void**)&km,   g_km);
    cudaGetSymbolAddress((void**)&vm,   g_vm);
    cudaGetSymbolAddress((void**)&attn, g_attn);
    cudaGetSymbolAddress((void**)&hb,   g_h);
    cudaGetSymbolAddress((void**)&h2,   g_h2);
    cudaGetSymbolAddress((void**)&Gp,   g_G);
    cudaGetSymbolAddress((void**)&Up,   g_U);
    cudaGetSymbolAddress((void**)&sc,   g_scores);

    // 1. rmsnorm1
    rmsnorm_k<<<T_, 256>>>(x, ln1, h1);

    // 2. QKV projections (+bias)
    GemmP p = {};
    p.zdiv = 1;
    p.A = h1; p.lda = D_; p.ldb = D_; p.ldc = D_;
    p.M = T_; p.N = D_; p.K = D_;
    p.B = qw; p.C = qm; p.X = qbias;
    sgemm_k<1><<<dim3(16,16,1), 256>>>(p);
    p.B = kw; p.C = km; p.X = kbias;
    sgemm_k<1><<<dim3(16,16,1), 256>>>(p);
    p.B = vw; p.C = vm; p.X = vbias;
    sgemm_k<1><<<dim3(16,16,1), 256>>>(p);

    // 3. RoPE on Q,K
    rope_k<<<(T_*H_*64)/256, 256>>>(pos, sint, cost);

    // 4. scores + softmax
    scores_k<<<dim3(S_/128, S_/128, B_*H_), 256>>>(qm, km, am);
    softmax_k<<<B_*H_*S_, 256>>>();

    // 5. P @ V  (batched over B*H)
    GemmP pv = {};
    pv.A = sc;   pv.lda = S_; pv.sA1 = (long long)H_*S_*S_; pv.sA2 = (long long)S_*S_;
    pv.B = vm;   pv.ldb = D_; pv.sB1 = (long long)S_*D_;    pv.sB2 = DH_;
    pv.C = attn; pv.ldc = D_; pv.sC1 = (long long)S_*D_;    pv.sC2 = DH_;
    pv.M = S_; pv.N = DH_; pv.K = S_; pv.zdiv = H_;
    sgemm_k<0><<<dim3(1, S_/128, B_*H_), 256>>>(pv);

    // 6. O projection + residual
    GemmP po = {};
    po.zdiv = 1;
    po.A = attn; po.lda = D_; po.B = ow; po.ldb = D_;
    po.C = hb;   po.ldc = D_; po.X = x;
    po.M = T_; po.N = D_; po.K = D_;
    sgemm_k<2><<<dim3(16,16,1), 256>>>(po);

    // 7. rmsnorm2, router, shared gate
    rmsnorm_k<<<T_, 256>>>(hb, ln2, h2);
    zero_k<<<(T_*D_)/256, 256>>>();
    router_k<<<T_, 256>>>(rw);
    sgate_k<<<T_, 256>>>(sgw);

    // 8. routed experts (gathered GEMMs, top-2 only)
    for (int e = 0; e < E_; e++) {
        moe_gu_k<<<dim3(I_/128, T_/128), 256>>>(eg + (long long)e*D_*I_, e, Gp);
        moe_gu_k<<<dim3(I_/128, T_/128), 256>>>(eu + (long long)e*D_*I_, e, Up);
        moe_down_k<<<dim3(D_/128, T_/128), 256>>>(ed + (long long)e*I_*D_, e);
    }

    // 9. shared expert gate/up
    GemmP ps = {};
    ps.zdiv = 1;
    ps.A = h2; ps.lda = D_; ps.ldb = IS_; ps.ldc = IS_;
    ps.M = T_; ps.N = IS_; ps.K = D_;
    ps.B = sg; ps.C = Gp;
    sgemm_k<0><<<dim3(IS_/128, T_/128, 1), 256>>>(ps);
    ps.B = su; ps.C = Up;
    sgemm_k<0><<<dim3(IS_/128, T_/128, 1), 256>>>(ps);

    // 10. shared down + final combine -> out
    shared_down_k<<<dim3(D_/128, T_/128, 1), 256>>>(sd, out);
}

// round 2
// speedup vs baseline: 2.6238x; 2.6238x over previous
#include <cuda_runtime.h>
#include <math.h>

#define B_ 2
#define S_ 1024
#define D_ 2048
#define H_ 16
#define DH_ 128
#define E_ 8
#define I_ 1408
#define IS_ 5632
#define T_ (B_*S_)
#define EPS_ 1e-6f

#define BM 128
#define BN 128
#define BK 16
#define PADA 4

typedef unsigned int u32;

// ---------------- static device scratch ----------------
__device__ float g_h1[T_*D_];
__device__ float g_qm[T_*D_];
__device__ float g_km[T_*D_];
__device__ float g_vm[T_*D_];
__device__ float g_attn[T_*D_];
__device__ float g_h[T_*D_];
__device__ float g_h2[T_*D_];
__device__ float g_moe[T_*D_];
__device__ float g_G[T_*IS_];
__device__ float g_U[T_*IS_];
__device__ float g_scores[(long long)B_*H_*S_*S_];
__device__ float g_sgate[T_];
__device__ int   g_cnt[E_];
__device__ int   g_list[E_*T_];
__device__ float g_wlist[E_*T_];

// ---------------- tf32 helpers ----------------
__device__ __forceinline__ u32 f2tf(float f) {
    u32 u; asm("cvt.rna.tf32.f32 %0, %1;" : "=r"(u) : "f"(f)); return u;
}

__device__ __forceinline__ void mma8(float* c, u32 a0,u32 a1,u32 a2,u32 a3,u32 b0,u32 b1) {
    asm volatile("mma.sync.aligned.m16n8k8.row.col.f32.tf32.tf32.f32 "
                 "{%0,%1,%2,%3},{%4,%5,%6,%7},{%8,%9},{%0,%1,%2,%3};"
                 : "+f"(c[0]), "+f"(c[1]), "+f"(c[2]), "+f"(c[3])
                 : "r"(a0), "r"(a1), "r"(a2), "r"(a3), "r"(b0), "r"(b1));
}

// warp computes 64x32 sub-tile at (m0,n0) from As[BK][BM+PADA], Bs[BK][BN+PADA]
__device__ __forceinline__ void compute_block(const u32 (*As)[BM+PADA], const u32 (*Bs)[BN+PADA],
                                              int m0, int n0, int g, int tg,
                                              float acc[4][4][4])
{
    #pragma unroll
    for (int ks = 0; ks < 2; ks++) {
        int k = ks * 8;
        u32 af[4][4]; u32 bf[4][2];
        #pragma unroll
        for (int mi = 0; mi < 4; mi++) {
            int rm = m0 + mi*16;
            af[mi][0] = As[k+tg  ][rm+g  ];
            af[mi][1] = As[k+tg  ][rm+g+8];
            af[mi][2] = As[k+tg+4][rm+g  ];
            af[mi][3] = As[k+tg+4][rm+g+8];
        }
        #pragma unroll
        for (int ni = 0; ni < 4; ni++) {
            int cb = n0 + ni*8;
            bf[ni][0] = Bs[k+tg  ][cb+g];
            bf[ni][1] = Bs[k+tg+4][cb+g];
        }
        #pragma unroll
        for (int mi = 0; mi < 4; mi++)
            #pragma unroll
            for (int ni = 0; ni < 4; ni++)
                mma8(acc[mi][ni], af[mi][0],af[mi][1],af[mi][2],af[mi][3],
                     bf[ni][0], bf[ni][1]);
    }
}

#define STORE_A(buf, v0, v1) do { \
    As[buf][aK+0][aRow] = f2tf((v0).x); As[buf][aK+1][aRow] = f2tf((v0).y); \
    As[buf][aK+2][aRow] = f2tf((v0).z); As[buf][aK+3][aRow] = f2tf((v0).w); \
    As[buf][aK+0][aRow+64] = f2tf((v1).x); As[buf][aK+1][aRow+64] = f2tf((v1).y); \
    As[buf][aK+2][aRow+64] = f2tf((v1).z); As[buf][aK+3][aRow+64] = f2tf((v1).w); } while(0)

#define STORE_B(buf, v0, v1) do { \
    Bs[buf][bK][bN+0] = f2tf((v0).x); Bs[buf][bK][bN+1] = f2tf((v0).y); \
    Bs[buf][bK][bN+2] = f2tf((v0).z); Bs[buf][bK][bN+3] = f2tf((v0).w); \
    Bs[buf][bK+8][bN+0] = f2tf((v1).x); Bs[buf][bK+8][bN+1] = f2tf((v1).y); \
    Bs[buf][bK+8][bN+2] = f2tf((v1).z); Bs[buf][bK+8][bN+3] = f2tf((v1).w); } while(0)

// ---------------- generic tensor-core GEMM ----------------
// MODE 0: C = A@B ; MODE 1: +bias X[col] ; MODE 2: +X[row,col]
struct GemmP {
    const float* A; const float* B; float* C; const float* X;
    int lda, ldb, ldc;
    int M, N, K;
    int zdiv;
    long long sA1, sA2, sB1, sB2, sC1, sC2;
};

template<int MODE>
__global__ __launch_bounds__(256)
void tgemm_k(GemmP p)
{
    __shared__ u32 As[2][BK][BM+PADA];
    __shared__ u32 Bs[2][BK][BN+PADA];
    int tid = threadIdx.x;
    int z = blockIdx.z;
    int z1 = z / p.zdiv, z2 = z - z1 * p.zdiv;
    const float* A  = p.A + z1*p.sA1 + z2*p.sA2;
    const float* Bm = p.B + z1*p.sB1 + z2*p.sB2;
    float*       C  = p.C + z1*p.sC1 + z2*p.sC2;
    const float* X  = p.X;
    if (MODE == 2) X += z1*p.sC1 + z2*p.sC2;

    int row0 = blockIdx.y * BM, col0 = blockIdx.x * BN;
    int lane = tid & 31, warp = tid >> 5;
    int g = lane >> 2, tg = lane & 3;
    int m0 = (warp & 1) * 64, n0 = (warp >> 1) * 32;
    int aRow = tid >> 2, aK = (tid & 3) * 4;
    int bK = tid >> 5, bN = (tid & 31) * 4;

    const float* Ap0 = A + (long long)(row0 + aRow) * p.lda + aK;
    const float* Ap1 = Ap0 + (long long)64 * p.lda;
    const float* Bp0 = Bm + (long long)bK * p.ldb + col0 + bN;
    const float* Bp1 = Bp0 + (long long)8 * p.ldb;

    float acc[4][4][4];
    #pragma unroll
    for (int i=0;i<4;i++) for (int j=0;j<4;j++) for (int q=0;q<4;q++) acc[i][j][q]=0.f;

    float4 a0 = *(const float4*)Ap0, a1 = *(const float4*)Ap1;
    float4 b0 = *(const float4*)Bp0, b1 = *(const float4*)Bp1;
    STORE_A(0, a0, a1); STORE_B(0, b0, b1);
    __syncthreads();

    int nt = p.K / BK;
    for (int kt = 0; kt < nt; kt++) {
        int buf = kt & 1;
        if (kt + 1 < nt) {
            int k0 = (kt+1) * BK;
            a0 = *(const float4*)(Ap0 + k0);
            a1 = *(const float4*)(Ap1 + k0);
            b0 = *(const float4*)(Bp0 + (long long)k0 * p.ldb);
            b1 = *(const float4*)(Bp1 + (long long)k0 * p.ldb);
        }
        compute_block(As[buf], Bs[buf], m0, n0, g, tg, acc);
        if (kt + 1 < nt) { STORE_A(buf^1, a0, a1); STORE_B(buf^1, b0, b1); }
        __syncthreads();
    }

    #pragma unroll
    for (int mi = 0; mi < 4; mi++) {
        #pragma unroll
        for (int ni = 0; ni < 4; ni++) {
            int r = row0 + m0 + mi*16 + g;
            int c = col0 + n0 + ni*8 + 2*tg;
            float v0 = acc[mi][ni][0], v1 = acc[mi][ni][1];
            float v2 = acc[mi][ni][2], v3 = acc[mi][ni][3];
            if (MODE == 1) { float x0=X[c], x1=X[c+1]; v0+=x0; v1+=x1; v2+=x0; v3+=x1; }
            if (MODE == 2) {
                v0 += X[(long long)r*p.ldc + c];     v1 += X[(long long)r*p.ldc + c + 1];
                v2 += X[(long long)(r+8)*p.ldc + c]; v3 += X[(long long)(r+8)*p.ldc + c + 1];
            }
            float* cp = C + (long long)r * p.ldc + c;
            cp[0] = v0; cp[1] = v1;
            cp += (long long)8 * p.ldc;
            cp[0] = v2; cp[1] = v3;
        }
    }
}

// ---------------- attention scores (tensor core, causal + mask) ----------------
__global__ __launch_bounds__(256)
void scores_t(const float* __restrict__ qmat, const float* __restrict__ kmat,
              const int* __restrict__ amask)
{
    int zz = blockIdx.z; int b = zz >> 4; int h = zz & 15;
    int row0 = blockIdx.y * BM, col0 = blockIdx.x * BN;
    float* C = g_scores + (long long)zz * S_ * S_;
    int tid = threadIdx.x;
    int lane = tid & 31, warp = tid >> 5;
    int g = lane >> 2, tg = lane & 3;
    int m0 = (warp & 1) * 64, n0 = (warp >> 1) * 32;

    if (col0 > row0 + 127) {
        #pragma unroll
        for (int mi = 0; mi < 4; mi++)
            #pragma unroll
            for (int ni = 0; ni < 4; ni++) {
                int r = row0 + m0 + mi*16 + g;
                int c = col0 + n0 + ni*8 + 2*tg;
                C[(long long)r*S_ + c] = -1e30f;     C[(long long)r*S_ + c+1] = -1e30f;
                C[(long long)(r+8)*S_ + c] = -1e30f; C[(long long)(r+8)*S_ + c+1] = -1e30f;
            }
        return;
    }

    __shared__ u32 As[2][BK][BM+PADA];
    __shared__ u32 Bs[2][BK][BN+PADA];
    const float* A  = qmat + (long long)b * S_ * D_ + h * DH_;
    const float* Km = kmat + (long long)b * S_ * D_ + h * DH_;

    int aRow = tid >> 2, aK = (tid & 3) * 4;   // A-style load for both operands
    const float* Ap0 = A  + (long long)(row0 + aRow) * D_ + aK;
    const float* Ap1 = Ap0 + (long long)64 * D_;
    const float* Kp0 = Km + (long long)(col0 + aRow) * D_ + aK;
    const float* Kp1 = Kp0 + (long long)64 * D_;

    float acc[4][4][4];
    #pragma unroll
    for (int i=0;i<4;i++) for (int j=0;j<4;j++) for (int q=0;q<4;q++) acc[i][j][q]=0.f;

    float4 a0 = *(const float4*)Ap0, a1 = *(const float4*)Ap1;
    float4 k0v = *(const float4*)Kp0, k1v = *(const float4*)Kp1;
    STORE_A(0, a0, a1);
    {   // B-store with A-style indices (transposed gather)
        Bs[0][aK+0][aRow] = f2tf(k0v.x); Bs[0][aK+1][aRow] = f2tf(k0v.y);
        Bs[0][aK+2][aRow] = f2tf(k0v.z); Bs[0][aK+3][aRow] = f2tf(k0v.w);
        Bs[0][aK+0][aRow+64] = f2tf(k1v.x); Bs[0][aK+1][aRow+64] = f2tf(k1v.y);
        Bs[0][aK+2][aRow+64] = f2tf(k1v.z); Bs[0][aK+3][aRow+64] = f2tf(k1v.w);
    }
    __syncthreads();

    int nt = DH_ / BK;  // 8
    for (int kt = 0; kt < nt; kt++) {
        int buf = kt & 1;
        if (kt + 1 < nt) {
            int k0 = (kt+1) * BK;
            a0 = *(const float4*)(Ap0 + k0);  a1 = *(const float4*)(Ap1 + k0);
            k0v = *(const float4*)(Kp0 + k0); k1v = *(const float4*)(Kp1 + k0);
        }
        compute_block(As[buf], Bs[buf], m0, n0, g, tg, acc);
        if (kt + 1 < nt) {
            int nb = buf ^ 1;
            STORE_A(nb, a0, a1);
            Bs[nb][aK+0][aRow] = f2tf(k0v.x); Bs[nb][aK+1][aRow] = f2tf(k0v.y);
            Bs[nb][aK+2][aRow] = f2tf(k0v.z); Bs[nb][aK+3][aRow] = f2tf(k0v.w);
            Bs[nb][aK+0][aRow+64] = f2tf(k1v.x); Bs[nb][aK+1][aRow+64] = f2tf(k1v.y);
            Bs[nb][aK+2][aRow+64] = f2tf(k1v.z); Bs[nb][aK+3][aRow+64] = f2tf(k1v.w);
        }
        __syncthreads();
    }

    const float scale = 0.08838834764831845f;
    #pragma unroll
    for (int mi = 0; mi < 4; mi++) {
        #pragma unroll
        for (int ni = 0; ni < 4; ni++) {
            int r = row0 + m0 + mi*16 + g;
            int c = col0 + n0 + ni*8 + 2*tg;
            #pragma unroll
            for (int q = 0; q < 4; q++) {
                int rr = r + (q >> 1) * 8;
                int cc = c + (q & 1);
                bool ok = (cc <= rr) && (amask[b*S_ + cc] != 0);
                C[(long long)rr * S_ + cc] = ok ? acc[mi][ni][q] * scale : -1e30f;
            }
        }
    }
}

// ---------------- MoE gathered gate/up GEMM (tensor core) ----------------
__global__ __launch_bounds__(256)
void moe_gu_t(const float* __restrict__ W, int e, float* __restrict__ Cout)
{
    int M = g_cnt[e];
    int row0 = blockIdx.y * BM;
    if (row0 >= M) return;
    int col0 = blockIdx.x * BN;
    __shared__ u32 As[2][BK][BM+PADA];
    __shared__ u32 Bs[2][BK][BN+PADA];
    __shared__ int toks[128];
    int tid = threadIdx.x;
    if (tid < 128) {
        int r = row0 + tid;
        toks[tid] = (r < M) ? g_list[e*T_ + r] : 0;
    }
    __syncthreads();
    int lane = tid & 31, warp = tid >> 5;
    int g = lane >> 2, tg = lane & 3;
    int m0 = (warp & 1) * 64, n0 = (warp >> 1) * 32;
    int aRow = tid >> 2, aK = (tid & 3) * 4;
    int bK = tid >> 5, bN = (tid & 31) * 4;

    const float* Ap0 = g_h2 + (long long)toks[aRow]    * D_ + aK;
    const float* Ap1 = g_h2 + (long long)toks[aRow+64] * D_ + aK;
    const float* Bp0 = W + (long long)bK * I_ + col0 + bN;
    const float* Bp1 = Bp0 + (long long)8 * I_;

    float acc[4][4][4];
    #pragma unroll
    for (int i=0;i<4;i++) for (int j=0;j<4;j++) for (int q=0;q<4;q++) acc[i][j][q]=0.f;

    float4 a0 = *(const float4*)Ap0, a1 = *(const float4*)Ap1;
    float4 b0 = *(const float4*)Bp0, b1 = *(const float4*)Bp1;
    STORE_A(0, a0, a1); STORE_B(0, b0, b1);
    __syncthreads();

    int nt = D_ / BK;
    for (int kt = 0; kt < nt; kt++) {
        int buf = kt & 1;
        if (kt + 1 < nt) {
            int k0 = (kt+1) * BK;
            a0 = *(const float4*)(Ap0 + k0);
            a1 = *(const float4*)(Ap1 + k0);
            b0 = *(const float4*)(Bp0 + (long long)k0 * I_);
            b1 = *(const float4*)(Bp1 + (long long)k0 * I_);
        }
        compute_block(As[buf], Bs[buf], m0, n0, g, tg, acc);
        if (kt + 1 < nt) { STORE_A(buf^1, a0, a1); STORE_B(buf^1, b0, b1); }
        __syncthreads();
    }

    #pragma unroll
    for (int mi = 0; mi < 4; mi++) {
        #pragma unroll
        for (int ni = 0; ni < 4; ni++) {
            int r = row0 + m0 + mi*16 + g;
            int c = col0 + n0 + ni*8 + 2*tg;
            if (r < M) {
                float* cp = Cout + (long long)r * I_ + c;
                cp[0] = acc[mi][ni][0]; cp[1] = acc[mi][ni][1];
            }
            if (r + 8 < M) {
                float* cp = Cout + (long long)(r+8) * I_ + c;
                cp[0] = acc[mi][ni][2]; cp[1] = acc[mi][ni][3];
            }
        }
    }
}

// ---------------- MoE down GEMM + scatter (tensor core) ----------------
__global__ __launch_bounds__(256)
void moe_down_t(const float* __restrict__ Wd, int e)
{
    int M = g_cnt[e];
    int row0 = blockIdx.y * BM;
    if (row0 >= M) return;
    int col0 = blockIdx.x * BN;
    __shared__ u32 As[2][BK][BM+PADA];
    __shared__ u32 Bs[2][BK][BN+PADA];
    __shared__ int toks[128];
    __shared__ float wexp[128];
    int tid = threadIdx.x;
    if (tid < 128) {
        int r = row0 + tid;
        toks[tid] = (r < M) ? g_list[e*T_ + r] : 0;
        wexp[tid] = (r < M) ? g_wlist[e*T_ + r] : 0.f;
    }
    __syncthreads();
    int lane = tid & 31, warp = tid >> 5;
    int g = lane >> 2, tg = lane & 3;
    int m0 = (warp & 1) * 64, n0 = (warp >> 1) * 32;
    int aRow = tid >> 2, aK = (tid & 3) * 4;
    int bK = tid >> 5, bN = (tid & 31) * 4;
    float w0 = wexp[aRow], w1 = wexp[aRow+64];

    long long ar0 = (long long)(row0 + aRow) * I_ + aK;
    long long ar1 = ar0 + (long long)64 * I_;
    const float* Bp0 = Wd + (long long)bK * D_ + col0 + bN;
    const float* Bp1 = Bp0 + (long long)8 * D_;

    float acc[4][4][4];
    #pragma unroll
    for (int i=0;i<4;i++) for (int j=0;j<4;j++) for (int q=0;q<4;q++) acc[i][j][q]=0.f;

    #define LOAD_ACT(K0, A0, A1) do { \
        float4 gv0 = *(const float4*)(g_G + ar0 + (K0)); \
        float4 uv0 = *(const float4*)(g_U + ar0 + (K0)); \
        float4 gv1 = *(const float4*)(g_G + ar1 + (K0)); \
        float4 uv1 = *(const float4*)(g_U + ar1 + (K0)); \
        (A0).x = (gv0.x/(1.f+expf(-gv0.x)))*uv0.x*w0; \
        (A0).y = (gv0.y/(1.f+expf(-gv0.y)))*uv0.y*w0; \
        (A0).z = (gv0.z/(1.f+expf(-gv0.z)))*uv0.z*w0; \
        (A0).w = (gv0.w/(1.f+expf(-gv0.w)))*uv0.w*w0; \
        (A1).x = (gv1.x/(1.f+expf(-gv1.x)))*uv1.x*w1; \
        (A1).y = (gv1.y/(1.f+expf(-gv1.y)))*uv1.y*w1; \
        (A1).z = (gv1.z/(1.f+expf(-gv1.z)))*uv1.z*w1; \
        (A1).w = (gv1.w/(1.f+expf(-gv1.w)))*uv1.w*w1; } while(0)

    float4 a0, a1, b0, b1;
    LOAD_ACT(0, a0, a1);
    b0 = *(const float4*)Bp0; b1 = *(const float4*)Bp1;
    STORE_A(0, a0, a1); STORE_B(0, b0, b1);
    __syncthreads();

    int nt = I_ / BK;
    for (int kt = 0; kt < nt; kt++) {
        int buf = kt & 1;
        if (kt + 1 < nt) {
            int k0 = (kt+1) * BK;
            LOAD_ACT(k0, a0, a1);
            b0 = *(const float4*)(Bp0 + (long long)k0 * D_);
            b1 = *(const float4*)(Bp1 + (long long)k0 * D_);
        }
        compute_block(As[buf], Bs[buf], m0, n0, g, tg, acc);
        if (kt + 1 < nt) { STORE_A(buf^1, a0, a1); STORE_B(buf^1, b0, b1); }
        __syncthreads();
    }
    #undef LOAD_ACT

    #pragma unroll
    for (int mi = 0; mi < 4; mi++) {
        #pragma unroll
        for (int ni = 0; ni < 4; ni++) {
            int r = row0 + m0 + mi*16 + g;
            int c = col0 + n0 + ni*8 + 2*tg;
            if (r < M) {
                int t = toks[m0 + mi*16 + g];
                float* cp = g_moe + (long long)t * D_ + c;
                cp[0] += acc[mi][ni][0]; cp[1] += acc[mi][ni][1];
            }
            if (r + 8 < M) {
                int t = toks[m0 + mi*16 + g + 8];
                float* cp = g_moe + (long long)t * D_ + c;
                cp[0] += acc[mi][ni][2]; cp[1] += acc[mi][ni][3];
            }
        }
    }
}

// ---------------- shared-expert down GEMM + final combine ----------------
__global__ __launch_bounds__(256)
void shared_down_t(const float* __restrict__ Wd, float* __restrict__ out)
{
    int row0 = blockIdx.y * BM, col0 = blockIdx.x * BN;
    __shared__ u32 As[2][BK][BM+PADA];
    __shared__ u32 Bs[2][BK][BN+PADA];
    int tid = threadIdx.x;
    int lane = tid & 31, warp = tid >> 5;
    int g = lane >> 2, tg = lane & 3;
    int m0 = (warp & 1) * 64, n0 = (warp >> 1) * 32;
    int aRow = tid >> 2, aK = (tid & 3) * 4;
    int bK = tid >> 5, bN = (tid & 31) * 4;

    long long ar0 = (long long)(row0 + aRow) * IS_ + aK;
    long long ar1 = ar0 + (long long)64 * IS_;
    const float* Bp0 = Wd + (long long)bK * D_ + col0 + bN;
    const float* Bp1 = Bp0 + (long long)8 * D_;

    float acc[4][4][4];
    #pragma unroll
    for (int i=0;i<4;i++) for (int j=0;j<4;j++) for (int q=0;q<4;q++) acc[i][j][q]=0.f;

    #define LOAD_ACT2(K0, A0, A1) do { \
        float4 gv0 = *(const float4*)(g_G + ar0 + (K0)); \
        float4 uv0 = *(const float4*)(g_U + ar0 + (K0)); \
        float4 gv1 = *(const float4*)(g_G + ar1 + (K0)); \
        float4 uv1 = *(const float4*)(g_U + ar1 + (K0)); \
        (A0).x = (gv0.x/(1.f+expf(-gv0.x)))*uv0.x; \
        (A0).y = (gv0.y/(1.f+expf(-gv0.y)))*uv0.y; \
        (A0).z = (gv0.z/(1.f+expf(-gv0.z)))*uv0.z; \
        (A0).w = (gv0.w/(1.f+expf(-gv0.w)))*uv0.w; \
        (A1).x = (gv1.x/(1.f+expf(-gv1.x)))*uv1.x; \
        (A1).y = (gv1.y/(1.f+expf(-gv1.y)))*uv1.y; \
        (A1).z = (gv1.z/(1.f+expf(-gv1.z)))*uv1.z; \
        (A1).w = (gv1.w/(1.f+expf(-gv1.w)))*uv1.w; } while(0)

    float4 a0, a1, b0, b1;
    LOAD_ACT2(0, a0, a1);
    b0 = *(const float4*)Bp0; b1 = *(const float4*)Bp1;
    STORE_A(0, a0, a1); STORE_B(0, b0, b1);
    __syncthreads();

    int nt = IS_ / BK;
    for (int kt = 0; kt < nt; kt++) {
        int buf = kt & 1;
        if (kt + 1 < nt) {
            int k0 = (kt+1) * BK;
            LOAD_ACT2(k0, a0, a1);
            b0 = *(const float4*)(Bp0 + (long long)k0 * D_);
            b1 = *(const float4*)(Bp1 + (long long)k0 * D_);
        }
        compute_block(As[buf], Bs[buf], m0, n0, g, tg, acc);
        if (kt + 1 < nt) { STORE_A(buf^1, a0, a1); STORE_B(buf^1, b0, b1); }
        __syncthreads();
    }
    #undef LOAD_ACT2

    #pragma unroll
    for (int mi = 0; mi < 4; mi++) {
        #pragma unroll
        for (int ni = 0; ni < 4; ni++) {
            int r = row0 + m0 + mi*16 + g;
            int c = col0 + n0 + ni*8 + 2*tg;
            float sg0 = g_sgate[r], sg1 = g_sgate[r+8];
            long long o0 = (long long)r * D_ + c;
            long long o1 = (long long)(r+8) * D_ + c;
            out[o0]   = g_h[o0]   + g_moe[o0]   + sg0 * acc[mi][ni][0];
            out[o0+1] = g_h[o0+1] + g_moe[o0+1] + sg0 * acc[mi][ni][1];
            out[o1]   = g_h[o1]   + g_moe[o1]   + sg1 * acc[mi][ni][2];
            out[o1+1] = g_h[o1+1] + g_moe[o1+1] + sg1 * acc[mi][ni][3];
        }
    }
}

// ---------------- small kernels (unchanged from R1) ----------------
__global__ void rmsnorm_k(const float* __restrict__ x, const float* __restrict__ w,
                          float* __restrict__ out)
{
    int t = blockIdx.x, tid = threadIdx.x;
    const float* xr = x + (long long)t * D_;
    float s = 0.f;
    #pragma unroll
    for (int i = 0; i < 8; i++) { float v = xr[tid + i*256]; s += v * v; }
    __shared__ float red[256];
    red[tid] = s; __syncthreads();
    for (int st = 128; st > 0; st >>= 1) {
        if (tid < st) red[tid] += red[tid + st];
        __syncthreads();
    }
    float r = rsqrtf(red[0] / (float)D_ + EPS_);
    float* orow = out + (long long)t * D_;
    #pragma unroll
    for (int i = 0; i < 8; i++) { int d = tid + i*256; orow[d] = xr[d] * r * w[d]; }
}

__global__ void rope_k(const int* __restrict__ pos,
                       const float* __restrict__ sint, const float* __restrict__ cost)
{
    int idx = blockIdx.x * blockDim.x + threadIdx.x;
    int d  = idx & 63;
    int hh = (idx >> 6) & 15;
    int t  = idx >> 10;
    int p = pos[t];
    long long base = (long long)t * D_ + hh * DH_;
    float c1 = cost[p*DH_ + d],      s1 = sint[p*DH_ + d];
    float c2 = cost[p*DH_ + d + 64], s2 = sint[p*DH_ + d + 64];
    float q1 = g_qm[base + d], q2 = g_qm[base + d + 64];
    g_qm[base + d]      = q1 * c1 - q2 * s1;
    g_qm[base + d + 64] = q2 * c2 + q1 * s2;
    float k1 = g_km[base + d], k2 = g_km[base + d + 64];
    g_km[base + d]      = k1 * c1 - k2 * s1;
    g_km[base + d + 64] = k2 * c2 + k1 * s2;
}

__global__ void softmax_k()
{
    long long row = blockIdx.x;
    float* p = g_scores + row * S_;
    int tid = threadIdx.x;
    __shared__ float red[256];
    float lv[4];
    #pragma unroll
    for (int i = 0; i < 4; i++) lv[i] = p[tid + i*256];
    float m = fmaxf(fmaxf(lv[0], lv[1]), fmaxf(lv[2], lv[3]));
    red[tid] = m; __syncthreads();
    for (int s = 128; s > 0; s >>= 1) {
        if (tid < s) red[tid] = fmaxf(red[tid], red[tid + s]);
        __syncthreads();
    }
    float mx = red[0]; __syncthreads();
    float sum = 0.f;
    #pragma unroll
    for (int i = 0; i < 4; i++) { lv[i] = expf(lv[i] - mx); sum += lv[i]; }
    red[tid] = sum; __syncthreads();
    for (int s = 128; s > 0; s >>= 1) {
        if (tid < s) red[tid] += red[tid + s];
        __syncthreads();
    }
    float inv = 1.0f / red[0];
    #pragma unroll
    for (int i = 0; i < 4; i++) p[tid + i*256] = lv[i] * inv;
}

__global__ void zero_k()
{
    long long i = (long long)blockIdx.x * 256 + threadIdx.x;
    g_moe[i] = 0.f;
    if (i < E_) g_cnt[i] = 0;
}

__global__ void router_k(const float* __restrict__ rw)
{
    int t = blockIdx.x, tid = threadIdx.x;
    __shared__ float red[256 * 8];
    float loc[8];
    #pragma unroll
    for (int e = 0; e < 8; e++) loc[e] = 0.f;
    const float* xr = g_h2 + (long long)t * D_;
    for (int d = tid; d < D_; d += 256) {
        float xv = xr[d];
        #pragma unroll
        for (int e = 0; e < 8; e++) loc[e] += xv * rw[d*E_ + e];
    }
    #pragma unroll
    for (int e = 0; e < 8; e++) red[e*256 + tid] = loc[e];
    __syncthreads();
    for (int s = 128; s > 0; s >>= 1) {
        if (tid < s) {
            #pragma unroll
            for (int e = 0; e < 8; e++) red[e*256 + tid] += red[e*256 + tid + s];
        }
        __syncthreads();
    }
    if (tid == 0) {
        float lg[8], pr[8];
        #pragma unroll
        for (int e = 0; e < 8; e++) lg[e] = red[e*256];
        float mx = lg[0];
        #pragma unroll
        for (int e = 1; e < 8; e++) mx = fmaxf(mx, lg[e]);
        float se = 0.f;
        #pragma unroll
        for (int e = 0; e < 8; e++) { pr[e] = expf(lg[e] - mx); se += pr[e]; }
        #pragma unroll
        for (int e = 0; e < 8; e++) pr[e] /= se;
        int i1 = 0;
        #pragma unroll
        for (int e = 1; e < 8; e++) if (pr[e] > pr[i1]) i1 = e;
        int i2 = (i1 == 0) ? 1 : 0;
        #pragma unroll
        for (int e = 0; e < 8; e++) if (e != i1 && pr[e] > pr[i2]) i2 = e;
        int s1 = atomicAdd(&g_cnt[i1], 1);
        g_list[i1*T_ + s1] = t; g_wlist[i1*T_ + s1] = pr[i1];
        int s2 = atomicAdd(&g_cnt[i2], 1);
        g_list[i2*T_ + s2] = t; g_wlist[i2*T_ + s2] = pr[i2];
    }
}

__global__ void sgate_k(const float* __restrict__ gw)
{
    int t = blockIdx.x, tid = threadIdx.x;
    const float* xr = g_h2 + (long long)t * D_;
    float s = 0.f;
    #pragma unroll
    for (int i = 0; i < 8; i++) { int d = tid + i*256; s += xr[d] * gw[d]; }
    __shared__ float red[256];
    red[tid] = s; __syncthreads();
    for (int st = 128; st > 0; st >>= 1) {
        if (tid < st) red[tid] += red[tid + st];
        __syncthreads();
    }
    if (tid == 0) g_sgate[t] = 1.f / (1.f + expf(-red[0]));
}

// ---------------- host launcher ----------------
extern "C" void kernel_launch(void* const* d_in, const int* in_sizes, int n_in,
                              void* d_out, int out_size)
{
    const float* x    = (const float*)d_in[0];
    const int*   pos  = (const int*)  d_in[1];
    const int*   am   = (const int*)  d_in[2];
    const float* sint = (const float*)d_in[3];
    const float* cost = (const float*)d_in[4];
    const float* ln1  = (const float*)d_in[5];
    const float* ln2  = (const float*)d_in[6];
    const float* qw   = (const float*)d_in[7];
    const float* qbias= (const float*)d_in[8];
    const float* kw   = (const float*)d_in[9];
    const float* kbias= (const float*)d_in[10];
    const float* vw   = (const float*)d_in[11];
    const float* vbias= (const float*)d_in[12];
    const float* ow   = (const float*)d_in[13];
    const float* rw   = (const float*)d_in[14];
    const float* eg   = (const float*)d_in[15];
    const float* eu   = (const float*)d_in[16];
    const float* ed   = (const float*)d_in[17];
    const float* sg   = (const float*)d_in[18];
    const float* su   = (const float*)d_in[19];
    const float* sd   = (const float*)d_in[20];
    const float* sgw  = (const float*)d_in[21];
    float* out = (float*)d_out;
    (void)in_sizes; (void)n_in; (void)out_size;

    float *h1, *qm, *km, *vm, *attn, *hb, *h2, *Gp, *Up, *sc;
    cudaGetSymbolAddress((void**)&h1,   g_h1);
    cudaGetSymbolAddress((void**)&qm,   g_qm);
    cudaGetSymbolAddress((void**)&km,   g_km);
    cudaGetSymbolAddress((void**)&vm,   g_vm);
    cudaGetSymbolAddress((void**)&attn, g_attn);
    cudaGetSymbolAddress((void**)&hb,   g_h);
    cudaGetSymbolAddress((void**)&h2,   g_h2);
    cudaGetSymbolAddress((void**)&Gp,   g_G);
    cudaGetSymbolAddress((void**)&Up,   g_U);
    cudaGetSymbolAddress((void**)&sc,   g_scores);

    // 1. rmsnorm1
    rmsnorm_k<<<T_, 256>>>(x, ln1, h1);

    // 2. QKV projections (+bias)
    GemmP p = {};
    p.zdiv = 1;
    p.A = h1; p.lda = D_; p.ldb = D_; p.ldc = D_;
    p.M = T_; p.N = D_; p.K = D_;
    p.B = qw; p.C = qm; p.X = qbias;
    tgemm_k<1><<<dim3(16,16,1), 256>>>(p);
    p.B = kw; p.C = km; p.X = kbias;
    tgemm_k<1><<<dim3(16,16,1), 256>>>(p);
    p.B = vw; p.C = vm; p.X = vbias;
    tgemm_k<1><<<dim3(16,16,1), 256>>>(p);

    // 3. RoPE
    rope_k<<<(T_*H_*64)/256, 256>>>(pos, sint, cost);

    // 4. scores + softmax
    scores_t<<<dim3(S_/128, S_/128, B_*H_), 256>>>(qm, km, am);
    softmax_k<<<B_*H_*S_, 256>>>();

    // 5. P @ V (batched over B*H)
    GemmP pv = {};
    pv.A = sc;   pv.lda = S_; pv.sA1 = (long long)H_*S_*S_; pv.sA2 = (long long)S_*S_;
    pv.B = vm;   pv.ldb = D_; pv.sB1 = (long long)S_*D_;    pv.sB2 = DH_;
    pv.C = attn; pv.ldc = D_; pv.sC1 = (long long)S_*D_;    pv.sC2 = DH_;
    pv.M = S_; pv.N = DH_; pv.K = S_; pv.zdiv = H_;
    tgemm_k<0><<<dim3(1, S_/128, B_*H_), 256>>>(pv);

    // 6. O projection + residual
    GemmP po = {};
    po.zdiv = 1;
    po.A = attn; po.lda = D_; po.B = ow; po.ldb = D_;
    po.C = hb;   po.ldc = D_; po.X = x;
    po.M = T_; po.N = D_; po.K = D_;
    tgemm_k<2><<<dim3(16,16,1), 256>>>(po);

    // 7. rmsnorm2, router, shared gate
    rmsnorm_k<<<T_, 256>>>(hb, ln2, h2);
    zero_k<<<(T_*D_)/256, 256>>>();
    router_k<<<T_, 256>>>(rw);
    sgate_k<<<T_, 256>>>(sgw);

    // 8. routed experts
    for (int e = 0; e < E_; e++) {
        moe_gu_t<<<dim3(I_/128, T_/128), 256>>>(eg + (long long)e*D_*I_, e, Gp);
        moe_gu_t<<<dim3(I_/128, T_/128), 256>>>(eu + (long long)e*D_*I_, e, Up);
        moe_down_t<<<dim3(D_/128, T_/128), 256>>>(ed + (long long)e*I_*D_, e);
    }

    // 9. shared expert gate/up
    GemmP ps = {};
    ps.zdiv = 1;
    ps.A = h2; ps.lda = D_; ps.ldb = IS_; ps.ldc = IS_;
    ps.M = T_; ps.N = IS_; ps.K = D_;
    ps.B = sg; ps.C = Gp;
    tgemm_k<0><<<dim3(IS_/128, T_/128, 1), 256>>>(ps);
    ps.B = su; ps.C = Up;
    tgemm_k<0><<<dim3(IS_/128, T_/128, 1), 256>>>(ps);

    // 10. shared down + final combine
    shared_down_t<<<dim3(D_/128, T_/128, 1), 256>>>(sd, out);
}

// round 4
// speedup vs baseline: 4.0679x; 1.5504x over previous
#include <cuda_runtime.h>
#include <math.h>

#define B_ 2
#define S_ 1024
#define D_ 2048
#define H_ 16
#define DH_ 128
#define E_ 8
#define I_ 1408
#define IS_ 5632
#define T_ (B_*S_)
#define EPS_ 1e-6f

#define BM 128
#define BN 128
#define BK 16
#define PADA 4
#define ITILES (I_/BN)   // 11

typedef unsigned int u32;

// ---------------- static device scratch ----------------
__device__ float g_h1[T_*D_];
__device__ float g_qm[T_*D_];
__device__ float g_km[T_*D_];
__device__ float g_vm[T_*D_];
__device__ float g_attn[T_*D_];
__device__ float g_h[T_*D_];
__device__ float g_h2[T_*D_];
__device__ float g_G[T_*IS_];            // shared-expert gate
__device__ float g_U[T_*IS_];            // shared-expert up
__device__ float g_eG[E_*T_*I_];         // per-expert gate slabs
__device__ float g_eU[E_*T_*I_];         // per-expert up slabs
__device__ float g_eD[(long long)E_*T_*D_];  // per-expert down output slabs
__device__ float g_scores[(long long)B_*H_*S_*S_];
__device__ float g_sgate[T_];
__device__ int   g_cnt[E_];
__device__ float g_wlist[E_*T_];
__device__ int   g_tok[E_*T_];           // expert -> token list
__device__ int   g_slot[T_*2];           // per-token slab rows (e*T_+slot)

// ---------------- tf32 helpers ----------------
__device__ __forceinline__ u32 f2tf(float f) {
    u32 u; asm("cvt.rna.tf32.f32 %0, %1;" : "=r"(u) : "f"(f)); return u;
}

__device__ __forceinline__ void mma8(float* c, u32 a0,u32 a1,u32 a2,u32 a3,u32 b0,u32 b1) {
    asm volatile("mma.sync.aligned.m16n8k8.row.col.f32.tf32.tf32.f32 "
                 "{%0,%1,%2,%3},{%4,%5,%6,%7},{%8,%9},{%0,%1,%2,%3};"
                 : "+f"(c[0]), "+f"(c[1]), "+f"(c[2]), "+f"(c[3])
                 : "r"(a0), "r"(a1), "r"(a2), "r"(a3), "r"(b0), "r"(b1));
}

__device__ __forceinline__ void compute_block(const u32 (*As)[BM+PADA], const u32 (*Bs)[BN+PADA],
                                              int m0, int n0, int g, int tg,
                                              float acc[4][4][4])
{
    #pragma unroll
    for (int ks = 0; ks < 2; ks++) {
        int k = ks * 8;
        u32 af[4][4]; u32 bf[4][2];
        #pragma unroll
        for (int mi = 0; mi < 4; mi++) {
            int rm = m0 + mi*16;
            af[mi][0] = As[k+tg  ][rm+g  ];
            af[mi][1] = As[k+tg  ][rm+g+8];
            af[mi][2] = As[k+tg+4][rm+g  ];
            af[mi][3] = As[k+tg+4][rm+g+8];
        }
        #pragma unroll
        for (int ni = 0; ni < 4; ni++) {
            int cb = n0 + ni*8;
            bf[ni][0] = Bs[k+tg  ][cb+g];
            bf[ni][1] = Bs[k+tg+4][cb+g];
        }
        #pragma unroll
        for (int mi = 0; mi < 4; mi++)
            #pragma unroll
            for (int ni = 0; ni < 4; ni++)
                mma8(acc[mi][ni], af[mi][0],af[mi][1],af[mi][2],af[mi][3],
                     bf[ni][0], bf[ni][1]);
    }
}

#define STORE_A(buf, v0, v1) do { \
    As[buf][aK+0][aRow] = f2tf((v0).x); As[buf][aK+1][aRow] = f2tf((v0).y); \
    As[buf][aK+2][aRow] = f2tf((v0).z); As[buf][aK+3][aRow] = f2tf((v0).w); \
    As[buf][aK+0][aRow+64] = f2tf((v1).x); As[buf][aK+1][aRow+64] = f2tf((v1).y); \
    As[buf][aK+2][aRow+64] = f2tf((v1).z); As[buf][aK+3][aRow+64] = f2tf((v1).w); } while(0)

#define STORE_B(buf, v0, v1) do { \
    Bs[buf][bK][bN+0] = f2tf((v0).x); Bs[buf][bK][bN+1] = f2tf((v0).y); \
    Bs[buf][bK][bN+2] = f2tf((v0).z); Bs[buf][bK][bN+3] = f2tf((v0).w); \
    Bs[buf][bK+8][bN+0] = f2tf((v1).x); Bs[buf][bK+8][bN+1] = f2tf((v1).y); \
    Bs[buf][bK+8][bN+2] = f2tf((v1).z); Bs[buf][bK+8][bN+3] = f2tf((v1).w); } while(0)

// ---------------- shared GEMM core ----------------
// MODE 0: C=A@B ; 1: +X[col] ; 2: +X[row,col]
template<int MODE>
__device__ __forceinline__ void gemm_core(const float* __restrict__ A,
                                          const float* __restrict__ Bm,
                                          float* __restrict__ C,
                                          const float* __restrict__ X,
                                          int lda, int ldb, int ldc, int K)
{
    __shared__ u32 As[2][BK][BM+PADA];
    __shared__ u32 Bs[2][BK][BN+PADA];
    int tid = threadIdx.x;
    int row0 = blockIdx.y * BM, col0 = blockIdx.x * BN;
    int lane = tid & 31, warp = tid >> 5;
    int g = lane >> 2, tg = lane & 3;
    int m0 = (warp & 1) * 64, n0 = (warp >> 1) * 32;
    int aRow = tid >> 2, aK = (tid & 3) * 4;
    int bK = tid >> 5, bN = (tid & 31) * 4;

    const float* Ap0 = A + (long long)(row0 + aRow) * lda + aK;
    const float* Ap1 = Ap0 + (long long)64 * lda;
    const float* Bp0 = Bm + (long long)bK * ldb + col0 + bN;
    const float* Bp1 = Bp0 + (long long)8 * ldb;

    float acc[4][4][4];
    #pragma unroll
    for (int i=0;i<4;i++) for (int j=0;j<4;j++) for (int q=0;q<4;q++) acc[i][j][q]=0.f;

    float4 a0 = *(const float4*)Ap0, a1 = *(const float4*)Ap1;
    float4 b0 = *(const float4*)Bp0, b1 = *(const float4*)Bp1;
    STORE_A(0, a0, a1); STORE_B(0, b0, b1);
    __syncthreads();

    int nt = K / BK;
    for (int kt = 0; kt < nt; kt++) {
        int buf = kt & 1;
        if (kt + 1 < nt) {
            int k0 = (kt+1) * BK;
            a0 = *(const float4*)(Ap0 + k0);
            a1 = *(const float4*)(Ap1 + k0);
            b0 = *(const float4*)(Bp0 + (long long)k0 * ldb);
            b1 = *(const float4*)(Bp1 + (long long)k0 * ldb);
        }
        compute_block(As[buf], Bs[buf], m0, n0, g, tg, acc);
        if (kt + 1 < nt) { STORE_A(buf^1, a0, a1); STORE_B(buf^1, b0, b1); }
        __syncthreads();
    }

    #pragma unroll
    for (int mi = 0; mi < 4; mi++) {
        #pragma unroll
        for (int ni = 0; ni < 4; ni++) {
            int r = row0 + m0 + mi*16 + g;
            int c = col0 + n0 + ni*8 + 2*tg;
            float v0 = acc[mi][ni][0], v1 = acc[mi][ni][1];
            float v2 = acc[mi][ni][2], v3 = acc[mi][ni][3];
            if (MODE == 1) { float x0=X[c], x1=X[c+1]; v0+=x0; v1+=x1; v2+=x0; v3+=x1; }
            if (MODE == 2) {
                v0 += X[(long long)r*ldc + c];     v1 += X[(long long)r*ldc + c + 1];
                v2 += X[(long long)(r+8)*ldc + c]; v3 += X[(long long)(r+8)*ldc + c + 1];
            }
            float* cp = C + (long long)r * ldc + c;
            cp[0] = v0; cp[1] = v1;
            cp += (long long)8 * ldc;
            cp[0] = v2; cp[1] = v3;
        }
    }
}

// ---------------- GEMM wrappers ----------------
struct GemmP {
    const float* A; const float* B; float* C; const float* X;
    int lda, ldb, ldc;
    int M, N, K;
    int zdiv;
    long long sA1, sA2, sB1, sB2, sC1, sC2;
};

template<int MODE>
__global__ __launch_bounds__(256)
void tgemm_k(GemmP p)
{
    int z = blockIdx.z;
    int z1 = z / p.zdiv, z2 = z - z1 * p.zdiv;
    const float* A  = p.A + z1*p.sA1 + z2*p.sA2;
    const float* Bm = p.B + z1*p.sB1 + z2*p.sB2;
    float*       C  = p.C + z1*p.sC1 + z2*p.sC2;
    const float* X  = p.X;
    if (MODE == 2) X += z1*p.sC1 + z2*p.sC2;
    gemm_core<MODE>(A, Bm, C, X, p.lda, p.ldb, p.ldc, p.K);
}

struct QKVP {
    const float *A, *w0, *w1, *w2, *b0, *b1, *b2;
    float *o0, *o1, *o2;
};

__global__ __launch_bounds__(256)
void qkv_t(QKVP p)
{
    int z = blockIdx.z;
    const float* Bm = (z == 0) ? p.w0 : (z == 1) ? p.w1 : p.w2;
    const float* X  = (z == 0) ? p.b0 : (z == 1) ? p.b1 : p.b2;
    float* C        = (z == 0) ? p.o0 : (z == 1) ? p.o1 : p.o2;
    gemm_core<1>(p.A, Bm, C, X, D_, D_, D_, D_);
}

__global__ __launch_bounds__(256)
void sgu_t(const float* __restrict__ sg, const float* __restrict__ su)
{
    int z = blockIdx.z;
    const float* Bm = z ? su : sg;
    float* C = z ? g_U : g_G;
    gemm_core<0>(g_h2, Bm, C, (const float*)0, D_, IS_, IS_, D_);
}

// ---------------- attention scores ----------------
__global__ __launch_bounds__(256)
void scores_t(const float* __restrict__ qmat, const float* __restrict__ kmat,
              const int* __restrict__ amask)
{
    int zz = blockIdx.z; int b = zz >> 4; int h = zz & 15;
    int row0 = blockIdx.y * BM, col0 = blockIdx.x * BN;
    if (col0 > row0 + 127) return;   // fully masked; softmax writes zeros there

    float* C = g_scores + (long long)zz * S_ * S_;
    int tid = threadIdx.x;
    int lane = tid & 31, warp = tid >> 5;
    int g = lane >> 2, tg = lane & 3;
    int m0 = (warp & 1) * 64, n0 = (warp >> 1) * 32;

    __shared__ u32 As[2][BK][BM+PADA];
    __shared__ u32 Bs[2][BK][BN+PADA];
    const float* A  = qmat + (long long)b * S_ * D_ + h * DH_;
    const float* Km = kmat + (long long)b * S_ * D_ + h * DH_;

    int aRow = tid >> 2, aK = (tid & 3) * 4;
    const float* Ap0 = A  + (long long)(row0 + aRow) * D_ + aK;
    const float* Ap1 = Ap0 + (long long)64 * D_;
    const float* Kp0 = Km + (long long)(col0 + aRow) * D_ + aK;
    const float* Kp1 = Kp0 + (long long)64 * D_;

    float acc[4][4][4];
    #pragma unroll
    for (int i=0;i<4;i++) for (int j=0;j<4;j++) for (int q=0;q<4;q++) acc[i][j][q]=0.f;

    float4 a0 = *(const float4*)Ap0, a1 = *(const float4*)Ap1;
    float4 k0v = *(const float4*)Kp0, k1v = *(const float4*)Kp1;
    STORE_A(0, a0, a1);
    {
        Bs[0][aK+0][aRow] = f2tf(k0v.x); Bs[0][aK+1][aRow] = f2tf(k0v.y);
        Bs[0][aK+2][aRow] = f2tf(k0v.z); Bs[0][aK+3][aRow] = f2tf(k0v.w);
        Bs[0][aK+0][aRow+64] = f2tf(k1v.x); Bs[0][aK+1][aRow+64] = f2tf(k1v.y);
        Bs[0][aK+2][aRow+64] = f2tf(k1v.z); Bs[0][aK+3][aRow+64] = f2tf(k1v.w);
    }
    __syncthreads();

    int nt = DH_ / BK;
    for (int kt = 0; kt < nt; kt++) {
        int buf = kt & 1;
        if (kt + 1 < nt) {
            int k0 = (kt+1) * BK;
            a0 = *(const float4*)(Ap0 + k0);  a1 = *(const float4*)(Ap1 + k0);
            k0v = *(const float4*)(Kp0 + k0); k1v = *(const float4*)(Kp1 + k0);
        }
        compute_block(As[buf], Bs[buf], m0, n0, g, tg, acc);
        if (kt + 1 < nt) {
            int nb = buf ^ 1;
            STORE_A(nb, a0, a1);
            Bs[nb][aK+0][aRow] = f2tf(k0v.x); Bs[nb][aK+1][aRow] = f2tf(k0v.y);
            Bs[nb][aK+2][aRow] = f2tf(k0v.z); Bs[nb][aK+3][aRow] = f2tf(k0v.w);
            Bs[nb][aK+0][aRow+64] = f2tf(k1v.x); Bs[nb][aK+1][aRow+64] = f2tf(k1v.y);
            Bs[nb][aK+2][aRow+64] = f2tf(k1v.z); Bs[nb][aK+3][aRow+64] = f2tf(k1v.w);
        }
        __syncthreads();
    }

    const float scale = 0.08838834764831845f;
    #pragma unroll
    for (int mi = 0; mi < 4; mi++) {
        #pragma unroll
        for (int ni = 0; ni < 4; ni++) {
            int r = row0 + m0 + mi*16 + g;
            int c = col0 + n0 + ni*8 + 2*tg;
            #pragma unroll
            for (int q = 0; q < 4; q++) {
                int rr = r + (q >> 1) * 8;
                int cc = c + (q & 1);
                bool ok = (cc <= rr) && (amask[b*S_ + cc] != 0);
                C[(long long)rr * S_ + cc] = ok ? acc[mi][ni][q] * scale : -1e30f;
            }
        }
    }
}

// ---------------- causal softmax (writes zeros above diagonal) ----------------
__global__ void softmax_k()
{
    int r = blockIdx.x & (S_ - 1);
    float* p = g_scores + (long long)blockIdx.x * S_;
    int tid = threadIdx.x;
    __shared__ float red[256];
    float lv[4];
    #pragma unroll
    for (int i = 0; i < 4; i++) {
        int c = tid + i*256;
        lv[i] = (c <= r) ? p[c] : -3.0e38f;
    }
    float m = fmaxf(fmaxf(lv[0], lv[1]), fmaxf(lv[2], lv[3]));
    red[tid] = m; __syncthreads();
    for (int s = 128; s > 0; s >>= 1) {
        if (tid < s) red[tid] = fmaxf(red[tid], red[tid + s]);
        __syncthreads();
    }
    float mx = red[0]; __syncthreads();
    float sum = 0.f;
    #pragma unroll
    for (int i = 0; i < 4; i++) {
        int c = tid + i*256;
        lv[i] = (c <= r) ? expf(lv[i] - mx) : 0.f;
        sum += lv[i];
    }
    red[tid] = sum; __syncthreads();
    for (int s = 128; s > 0; s >>= 1) {
        if (tid < s) red[tid] += red[tid + s];
        __syncthreads();
    }
    float inv = 1.0f / red[0];
    #pragma unroll
    for (int i = 0; i < 4; i++) p[tid + i*256] = lv[i] * inv;
}

// ---------------- MoE gate/up for ALL experts (one launch) ----------------
__global__ __launch_bounds__(256)
void moe_gu_all(const float* __restrict__ eg, const float* __restrict__ eu)
{
    int e = blockIdx.z;
    int M = g_cnt[e];
    int row0 = blockIdx.y * BM;
    if (row0 >= M) return;
    int bx = blockIdx.x;
    int isUp = (bx >= ITILES) ? 1 : 0;
    int col0 = (isUp ? bx - ITILES : bx) * BN;
    const float* W = (isUp ? eu : eg) + (long long)e * D_ * I_;
    float* Cout = (isUp ? g_eU : g_eG) + (long long)e * T_ * I_;

    __shared__ u32 As[2][BK][BM+PADA];
    __shared__ u32 Bs[2][BK][BN+PADA];
    __shared__ int toks[128];
    int tid = threadIdx.x;
    if (tid < 128) {
        int r = row0 + tid;
        toks[tid] = (r < M) ? g_tok[e*T_ + r] : 0;
    }
    __syncthreads();

    int lane = tid & 31, warp = tid >> 5;
    int g = lane >> 2, tg = lane & 3;
    int m0 = (warp & 1) * 64, n0 = (warp >> 1) * 32;
    int aRow = tid >> 2, aK = (tid & 3) * 4;
    int bK = tid >> 5, bN = (tid & 31) * 4;

    const float* Ap0 = g_h2 + (long long)toks[aRow]    * D_ + aK;
    const float* Ap1 = g_h2 + (long long)toks[aRow+64] * D_ + aK;
    const float* Bp0 = W + (long long)bK * I_ + col0 + bN;
    const float* Bp1 = Bp0 + (long long)8 * I_;

    float acc[4][4][4];
    #pragma unroll
    for (int i=0;i<4;i++) for (int j=0;j<4;j++) for (int q=0;q<4;q++) acc[i][j][q]=0.f;

    float4 a0 = *(const float4*)Ap0, a1 = *(const float4*)Ap1;
    float4 b0 = *(const float4*)Bp0, b1 = *(const float4*)Bp1;
    STORE_A(0, a0, a1); STORE_B(0, b0, b1);
    __syncthreads();

    int nt = D_ / BK;
    for (int kt = 0; kt < nt; kt++) {
        int buf = kt & 1;
        if (kt + 1 < nt) {
            int k0 = (kt+1) * BK;
            a0 = *(const float4*)(Ap0 + k0);
            a1 = *(const float4*)(Ap1 + k0);
            b0 = *(const float4*)(Bp0 + (long long)k0 * I_);
            b1 = *(const float4*)(Bp1 + (long long)k0 * I_);
        }
        compute_block(As[buf], Bs[buf], m0, n0, g, tg, acc);
        if (kt + 1 < nt) { STORE_A(buf^1, a0, a1); STORE_B(buf^1, b0, b1); }
        __syncthreads();
    }

    #pragma unroll
    for (int mi = 0; mi < 4; mi++) {
        #pragma unroll
        for (int ni = 0; ni < 4; ni++) {
            int r = row0 + m0 + mi*16 + g;
            int c = col0 + n0 + ni*8 + 2*tg;
            if (r < M) {
                float* cp = Cout + (long long)r * I_ + c;
                cp[0] = acc[mi][ni][0]; cp[1] = acc[mi][ni][1];
            }
            if (r + 8 < M) {
                float* cp = Cout + (long long)(r+8) * I_ + c;
                cp[0] = acc[mi][ni][2]; cp[1] = acc[mi][ni][3];
            }
        }
    }
}

// ---------------- MoE down for ALL experts (one launch) ----------------
__global__ __launch_bounds__(256)
void moe_down_all(const float* __restrict__ ed)
{
    int e = blockIdx.z;
    int M = g_cnt[e];
    int row0 = blockIdx.y * BM;
    if (row0 >= M) return;
    int col0 = blockIdx.x * BN;
    const float* Wd = ed + (long long)e * I_ * D_;
    const float* Gs = g_eG + (long long)e * T_ * I_;
    const float* Us = g_eU + (long long)e * T_ * I_;
    float* Dout = g_eD + (long long)e * T_ * D_;

    __shared__ u32 As[2][BK][BM+PADA];
    __shared__ u32 Bs[2][BK][BN+PADA];
    __shared__ float wexp[128];
    int tid = threadIdx.x;
    if (tid < 128) {
        int r = row0 + tid;
        wexp[tid] = (r < M) ? g_wlist[e*T_ + r] : 0.f;
    }
    __syncthreads();

    int lane = tid & 31, warp = tid >> 5;
    int g = lane >> 2, tg = lane & 3;
    int m0 = (warp & 1) * 64, n0 = (warp >> 1) * 32;
    int aRow = tid >> 2, aK = (tid & 3) * 4;
    int bK = tid >> 5, bN = (tid & 31) * 4;
    float w0 = wexp[aRow], w1 = wexp[aRow+64];

    long long ar0 = (long long)(row0 + aRow) * I_ + aK;
    long long ar1 = ar0 + (long long)64 * I_;
    const float* Bp0 = Wd + (long long)bK * D_ + col0 + bN;
    const float* Bp1 = Bp0 + (long long)8 * D_;

    float acc[4][4][4];
    #pragma unroll
    for (int i=0;i<4;i++) for (int j=0;j<4;j++) for (int q=0;q<4;q++) acc[i][j][q]=0.f;

    #define LOAD_ACT(K0, A0, A1) do { \
        float4 gv0 = *(const float4*)(Gs + ar0 + (K0)); \
        float4 uv0 = *(const float4*)(Us + ar0 + (K0)); \
        float4 gv1 = *(const float4*)(Gs + ar1 + (K0)); \
        float4 uv1 = *(const float4*)(Us + ar1 + (K0)); \
        (A0).x = (gv0.x/(1.f+expf(-gv0.x)))*uv0.x*w0; \
        (A0).y = (gv0.y/(1.f+expf(-gv0.y)))*uv0.y*w0; \
        (A0).z = (gv0.z/(1.f+expf(-gv0.z)))*uv0.z*w0; \
        (A0).w = (gv0.w/(1.f+expf(-gv0.w)))*uv0.w*w0; \
        (A1).x = (gv1.x/(1.f+expf(-gv1.x)))*uv1.x*w1; \
        (A1).y = (gv1.y/(1.f+expf(-gv1.y)))*uv1.y*w1; \
        (A1).z = (gv1.z/(1.f+expf(-gv1.z)))*uv1.z*w1; \
        (A1).w = (gv1.w/(1.f+expf(-gv1.w)))*uv1.w*w1; } while(0)

    float4 a0, a1, b0, b1;
    LOAD_ACT(0, a0, a1);
    b0 = *(const float4*)Bp0; b1 = *(const float4*)Bp1;
    STORE_A(0, a0, a1); STORE_B(0, b0, b1);
    __syncthreads();

    int nt = I_ / BK;
    for (int kt = 0; kt < nt; kt++) {
        int buf = kt & 1;
        if (kt + 1 < nt) {
            int k0 = (kt+1) * BK;
            LOAD_ACT(k0, a0, a1);
            b0 = *(const float4*)(Bp0 + (long long)k0 * D_);
            b1 = *(const float4*)(Bp1 + (long long)k0 * D_);
        }
        compute_block(As[buf], Bs[buf], m0, n0, g, tg, acc);
        if (kt + 1 < nt) { STORE_A(buf^1, a0, a1); STORE_B(buf^1, b0, b1); }
        __syncthreads();
    }
    #undef LOAD_ACT

    #pragma unroll
    for (int mi = 0; mi < 4; mi++) {
        #pragma unroll
        for (int ni = 0; ni < 4; ni++) {
            int r = row0 + m0 + mi*16 + g;
            int c = col0 + n0 + ni*8 + 2*tg;
            float* cp0 = Dout + (long long)r * D_ + c;
            cp0[0] = acc[mi][ni][0]; cp0[1] = acc[mi][ni][1];
            float* cp1 = Dout + (long long)(r+8) * D_ + c;
            cp1[0] = acc[mi][ni][2]; cp1[1] = acc[mi][ni][3];
        }
    }
}

// ---------------- shared-expert down GEMM + final combine ----------------
__global__ __launch_bounds__(256)
void shared_down_t(const float* __restrict__ Wd, float* __restrict__ out)
{
    int row0 = blockIdx.y * BM, col0 = blockIdx.x * BN;
    __shared__ u32 As[2][BK][BM+PADA];
    __shared__ u32 Bs[2][BK][BN+PADA];
    int tid = threadIdx.x;
    int lane = tid & 31, warp = tid >> 5;
    int g = lane >> 2, tg = lane & 3;
    int m0 = (warp & 1) * 64, n0 = (warp >> 1) * 32;
    int aRow = tid >> 2, aK = (tid & 3) * 4;
    int bK = tid >> 5, bN = (tid & 31) * 4;

    long long ar0 = (long long)(row0 + aRow) * IS_ + aK;
    long long ar1 = ar0 + (long long)64 * IS_;
    const float* Bp0 = Wd + (long long)bK * D_ + col0 + bN;
    const float* Bp1 = Bp0 + (long long)8 * D_;

    float acc[4][4][4];
    #pragma unroll
    for (int i=0;i<4;i++) for (int j=0;j<4;j++) for (int q=0;q<4;q++) acc[i][j][q]=0.f;

    #define LOAD_ACT2(K0, A0, A1) do { \
        float4 gv0 = *(const float4*)(g_G + ar0 + (K0)); \
        float4 uv0 = *(const float4*)(g_U + ar0 + (K0)); \
        float4 gv1 = *(const float4*)(g_G + ar1 + (K0)); \
        float4 uv1 = *(const float4*)(g_U + ar1 + (K0)); \
        (A0).x = (gv0.x/(1.f+expf(-gv0.x)))*uv0.x; \
        (A0).y = (gv0.y/(1.f+expf(-gv0.y)))*uv0.y; \
        (A0).z = (gv0.z/(1.f+expf(-gv0.z)))*uv0.z; \
        (A0).w = (gv0.w/(1.f+expf(-gv0.w)))*uv0.w; \
        (A1).x = (gv1.x/(1.f+expf(-gv1.x)))*uv1.x; \
        (A1).y = (gv1.y/(1.f+expf(-gv1.y)))*uv1.y; \
        (A1).z = (gv1.z/(1.f+expf(-gv1.z)))*uv1.z; \
        (A1).w = (gv1.w/(1.f+expf(-gv1.w)))*uv1.w; } while(0)

    float4 a0, a1, b0, b1;
    LOAD_ACT2(0, a0, a1);
    b0 = *(const float4*)Bp0; b1 = *(const float4*)Bp1;
    STORE_A(0, a0, a1); STORE_B(0, b0, b1);
    __syncthreads();

    int nt = IS_ / BK;
    for (int kt = 0; kt < nt; kt++) {
        int buf = kt & 1;
        if (kt + 1 < nt) {
            int k0 = (kt+1) * BK;
            LOAD_ACT2(k0, a0, a1);
            b0 = *(const float4*)(Bp0 + (long long)k0 * D_);
            b1 = *(const float4*)(Bp1 + (long long)k0 * D_);
        }
        compute_block(As[buf], Bs[buf], m0, n0, g, tg, acc);
        if (kt + 1 < nt) { STORE_A(buf^1, a0, a1); STORE_B(buf^1, b0, b1); }
        __syncthreads();
    }
    #undef LOAD_ACT2

    #pragma unroll
    for (int mi = 0; mi < 4; mi++) {
        int r = row0 + m0 + mi*16 + g;
        int sa0 = g_slot[2*r],       sb0 = g_slot[2*r+1];
        int sa1 = g_slot[2*(r+8)],   sb1 = g_slot[2*(r+8)+1];
        float sg0 = g_sgate[r], sg1 = g_sgate[r+8];
        #pragma unroll
        for (int ni = 0; ni < 4; ni++) {
            int c = col0 + n0 + ni*8 + 2*tg;
            long long o0 = (long long)r * D_ + c;
            long long o1 = (long long)(r+8) * D_ + c;
            long long ma0 = (long long)sa0 * D_ + c, mb0 = (long long)sb0 * D_ + c;
            long long ma1 = (long long)sa1 * D_ + c, mb1 = (long long)sb1 * D_ + c;
            out[o0]   = g_h[o0]   + g_eD[ma0]   + g_eD[mb0]   + sg0 * acc[mi][ni][0];
            out[o0+1] = g_h[o0+1] + g_eD[ma0+1] + g_eD[mb0+1] + sg0 * acc[mi][ni][1];
            out[o1]   = g_h[o1]   + g_eD[ma1]   + g_eD[mb1]   + sg1 * acc[mi][ni][2];
            out[o1+1] = g_h[o1+1] + g_eD[ma1+1] + g_eD[mb1+1] + sg1 * acc[mi][ni][3];
        }
    }
}

// ---------------- small kernels ----------------
__global__ void rmsnorm_k(const float* __restrict__ x, const float* __restrict__ w,
                          float* __restrict__ out)
{
    int t = blockIdx.x, tid = threadIdx.x;
    const float* xr = x + (long long)t * D_;
    float s = 0.f;
    #pragma unroll
    for (int i = 0; i < 8; i++) { float v = xr[tid + i*256]; s += v * v; }
    __shared__ float red[256];
    red[tid] = s; __syncthreads();
    for (int st = 128; st > 0; st >>= 1) {
        if (tid < st) red[tid] += red[tid + st];
        __syncthreads();
    }
    float r = rsqrtf(red[0] / (float)D_ + EPS_);
    float* orow = out + (long long)t * D_;
    #pragma unroll
    for (int i = 0; i < 8; i++) { int d = tid + i*256; orow[d] = xr[d] * r * w[d]; }
}

__global__ void rope_k(const int* __restrict__ pos,
                       const float* __restrict__ sint, const float* __restrict__ cost)
{
    int idx = blockIdx.x * blockDim.x + threadIdx.x;
    int d  = idx & 63;
    int hh = (idx >> 6) & 15;
    int t  = idx >> 10;
    int p = pos[t];
    long long base = (long long)t * D_ + hh * DH_;
    float c1 = cost[p*DH_ + d],      s1 = sint[p*DH_ + d];
    float c2 = cost[p*DH_ + d + 64], s2 = sint[p*DH_ + d + 64];
    float q1 = g_qm[base + d], q2 = g_qm[base + d + 64];
    g_qm[base + d]      = q1 * c1 - q2 * s1;
    g_qm[base + d + 64] = q2 * c2 + q1 * s2;
    float k1 = g_km[base + d], k2 = g_km[base + d + 64];
    g_km[base + d]      = k1 * c1 - k2 * s1;
    g_km[base + d + 64] = k2 * c2 + k1 * s2;
}

__global__ void zero_cnt_k() { if (threadIdx.x < E_) g_cnt[threadIdx.x] = 0; }

__global__ void router_k(const float* __restrict__ rw)
{
    int t = blockIdx.x, tid = threadIdx.x;
    __shared__ float red[256 * 8];
    float loc[8];
    #pragma unroll
    for (int e = 0; e < 8; e++) loc[e] = 0.f;
    const float* xr = g_h2 + (long long)t * D_;
    for (int d = tid; d < D_; d += 256) {
        float xv = xr[d];
        #pragma unroll
        for (int e = 0; e < 8; e++) loc[e] += xv * rw[d*E_ + e];
    }
    #pragma unroll
    for (int e = 0; e < 8; e++) red[e*256 + tid] = loc[e];
    __syncthreads();
    for (int s = 128; s > 0; s >>= 1) {
        if (tid < s) {
            #pragma unroll
            for (int e = 0; e < 8; e++) red[e*256 + tid] += red[e*256 + tid + s];
        }
        __syncthreads();
    }
    if (tid == 0) {
        float lg[8], pr[8];
        #pragma unroll
        for (int e = 0; e < 8; e++) lg[e] = red[e*256];
        float mx = lg[0];
        #pragma unroll
        for (int e = 1; e < 8; e++) mx = fmaxf(mx, lg[e]);
        float se = 0.f;
        #pragma unroll
        for (int e = 0; e < 8; e++) { pr[e] = expf(lg[e] - mx); se += pr[e]; }
        #pragma unroll
        for (int e = 0; e < 8; e++) pr[e] /= se;
        int i1 = 0;
        #pragma unroll
        for (int e = 1; e < 8; e++) if (pr[e] > pr[i1]) i1 = e;
        int i2 = (i1 == 0) ? 1 : 0;
        #pragma unroll
        for (int e = 0; e < 8; e++) if (e != i1 && pr[e] > pr[i2]) i2 = e;
        int s1 = atomicAdd(&g_cnt[i1], 1);
        g_tok[i1*T_ + s1] = t; g_wlist[i1*T_ + s1] = pr[i1];
        g_slot[2*t] = i1*T_ + s1;
        int s2 = atomicAdd(&g_cnt[i2], 1);
        g_tok[i2*T_ + s2] = t; g_wlist[i2*T_ + s2] = pr[i2];
        g_slot[2*t+1] = i2*T_ + s2;
    }
}

__global__ void sgate_k(const float* __restrict__ gw)
{
    int t = blockIdx.x, tid = threadIdx.x;
    const float* xr = g_h2 + (long long)t * D_;
    float s = 0.f;
    #pragma unroll
    for (int i = 0; i < 8; i++) { int d = tid + i*256; s += xr[d] * gw[d]; }
    __shared__ float red[256];
    red[tid] = s; __syncthreads();
    for (int st = 128; st > 0; st >>= 1) {
        if (tid < st) red[tid] += red[tid + st];
        __syncthreads();
    }
    if (tid == 0) g_sgate[t] = 1.f / (1.f + expf(-red[0]));
}

// ---------------- host launcher ----------------
extern "C" void kernel_launch(void* const* d_in, const int* in_sizes, int n_in,
                              void* d_out, int out_size)
{
    const float* x    = (const float*)d_in[0];
    const int*   pos  = (const int*)  d_in[1];
    const int*   am   = (const int*)  d_in[2];
    const float* sint = (const float*)d_in[3];
    const float* cost = (const float*)d_in[4];
    const float* ln1  = (const float*)d_in[5];
    const float* ln2  = (const float*)d_in[6];
    const float* qw   = (const float*)d_in[7];
    const float* qbias= (const float*)d_in[8];
    const float* kw   = (const float*)d_in[9];
    const float* kbias= (const float*)d_in[10];
    const float* vw   = (const float*)d_in[11];
    const float* vbias= (const float*)d_in[12];
    const float* ow   = (const float*)d_in[13];
    const float* rw   = (const float*)d_in[14];
    const float* eg   = (const float*)d_in[15];
    const float* eu   = (const float*)d_in[16];
    const float* ed   = (const float*)d_in[17];
    const float* sg   = (const float*)d_in[18];
    const float* su   = (const float*)d_in[19];
    const float* sd   = (const float*)d_in[20];
    const float* sgw  = (const float*)d_in[21];
    float* out = (float*)d_out;
    (void)in_sizes; (void)n_in; (void)out_size;

    float *h1, *qm, *km, *vm, *attn, *hb, *h2, *sc;
    cudaGetSymbolAddress((void**)&h1,   g_h1);
    cudaGetSymbolAddress((void**)&qm,   g_qm);
    cudaGetSymbolAddress((void**)&km,   g_km);
    cudaGetSymbolAddress((void**)&vm,   g_vm);
    cudaGetSymbolAddress((void**)&attn, g_attn);
    cudaGetSymbolAddress((void**)&hb,   g_h);
    cudaGetSymbolAddress((void**)&h2,   g_h2);
    cudaGetSymbolAddress((void**)&sc,   g_scores);

    // 1. rmsnorm1
    rmsnorm_k<<<T_, 256>>>(x, ln1, h1);

    // 2. QKV merged
    QKVP q = { h1, qw, kw, vw, qbias, kbias, vbias, qm, km, vm };
    qkv_t<<<dim3(D_/BN, T_/BM, 3), 256>>>(q);

    // 3. RoPE
    rope_k<<<(T_*H_*64)/256, 256>>>(pos, sint, cost);

    // 4. scores + causal softmax
    scores_t<<<dim3(S_/128, S_/128, B_*H_), 256>>>(qm, km, am);
    softmax_k<<<B_*H_*S_, 256>>>();

    // 5. P @ V (batched over B*H)
    GemmP pv = {};
    pv.A = sc;   pv.lda = S_; pv.sA1 = (long long)H_*S_*S_; pv.sA2 = (long long)S_*S_;
    pv.B = vm;   pv.ldb = D_; pv.sB1 = (long long)S_*D_;    pv.sB2 = DH_;
    pv.C = attn; pv.ldc = D_; pv.sC1 = (long long)S_*D_;    pv.sC2 = DH_;
    pv.M = S_; pv.N = DH_; pv.K = S_; pv.zdiv = H_;
    tgemm_k<0><<<dim3(1, S_/128, B_*H_), 256>>>(pv);

    // 6. O projection + residual
    GemmP po = {};
    po.zdiv = 1;
    po.A = attn; po.lda = D_; po.B = ow; po.ldb = D_;
    po.C = hb;   po.ldc = D_; po.X = x;
    po.M = T_; po.N = D_; po.K = D_;
    tgemm_k<2><<<dim3(16,16,1), 256>>>(po);

    // 7. rmsnorm2, router, shared gate
    rmsnorm_k<<<T_, 256>>>(hb, ln2, h2);
    zero_cnt_k<<<1, 32>>>();
    router_k<<<T_, 256>>>(rw);
    sgate_k<<<T_, 256>>>(sgw);

    // 8. routed experts — all experts in two launches
    moe_gu_all<<<dim3(2*ITILES, T_/BM, E_), 256>>>(eg, eu);
    moe_down_all<<<dim3(D_/BN, T_/BM, E_), 256>>>(ed);

    // 9. shared expert gate/up merged
    sgu_t<<<dim3(IS_/BN, T_/BM, 2), 256>>>(sg, su);

    // 10. shared down + final combine
    shared_down_t<<<dim3(D_/BN, T_/BM, 1), 256>>>(sd, out);
}